// round 1
// baseline (speedup 1.0000x reference)
#include <cuda_runtime.h>
#include <cstdint>
#include <math.h>

// Problem constants
#define NROWS 131072   // 32*64*64
#define DDIM  64
#define KCB   512

// Output layout (flattened tuple, float32):
// quantized_st [NROWS*DDIM], loss [1], perplexity [1], new_embeddings [DDIM*KCB], encoding_indices [NROWS]
#define OFF_Q    0
#define OFF_LOSS (NROWS * DDIM)                 // 8388608
#define OFF_PERP (OFF_LOSS + 1)                 // 8388609
#define OFF_EMB  (OFF_PERP + 1)                 // 8388610
#define OFF_IDX  (OFF_EMB + DDIM * KCB)         // 8421378

// Device scratch (no allocations allowed)
__device__ float g_dw[DDIM * KCB];
__device__ float g_cluster[KCB];
__device__ float g_loss;
__device__ float g_enorm[KCB];

// ---------------------------------------------------------------------------
// Init: zero accumulators, compute ||e_k||^2
// ---------------------------------------------------------------------------
__global__ void k_init(const float* __restrict__ emb) {
    int t = blockIdx.x * 512 + threadIdx.x;
    if (t < DDIM * KCB) g_dw[t] = 0.f;
    if (blockIdx.x == 0) {
        int k = threadIdx.x;
        g_cluster[k] = 0.f;
        if (k == 0) g_loss = 0.f;
        float s = 0.f;
#pragma unroll
        for (int d = 0; d < DDIM; d++) {
            float e = emb[d * KCB + k];
            s = fmaf(e, e, s);
        }
        g_enorm[k] = s;
    }
}

// ---------------------------------------------------------------------------
// Main: per-row nearest code + quantize + loss + histogram + dw scatter
// ---------------------------------------------------------------------------
__global__ __launch_bounds__(512, 1)
void k_main(const float* __restrict__ x,
            const float* __restrict__ emb,
            float* __restrict__ out_q,
            float* __restrict__ out_idx) {
    extern __shared__ float smem[];
    float* s_emb   = smem;                       // [DDIM][KCB] = 32768 floats
    float* s_enorm = smem + DDIM * KCB;          // 512 floats
    int*   s_hist  = (int*)(smem + DDIM * KCB + KCB); // 512 ints

    const int tid = threadIdx.x;

    // Stage embeddings + norms into shared
    for (int i = tid; i < DDIM * KCB; i += 512) s_emb[i] = emb[i];
    if (tid < KCB) { s_enorm[tid] = g_enorm[tid]; s_hist[tid] = 0; }
    __syncthreads();

    const int row = blockIdx.x * 512 + tid;

    // Load x row into registers
    float xr[DDIM];
    {
        const float4* xp = reinterpret_cast<const float4*>(x + (size_t)row * DDIM);
#pragma unroll
        for (int i = 0; i < DDIM / 4; i++) {
            float4 v = xp[i];
            xr[4*i+0] = v.x; xr[4*i+1] = v.y; xr[4*i+2] = v.z; xr[4*i+3] = v.w;
        }
    }

    float best = 3.4e38f;
    int   bidx = 0;

    // Process K in chunks of 16 codes = 8 packed f32x2 accumulators.
    // acc[j] halves accumulate dot(x, e_{k0+2j}) and dot(x, e_{k0+2j+1}).
#pragma unroll 1
    for (int k0 = 0; k0 < KCB; k0 += 16) {
        unsigned long long acc0 = 0ull, acc1 = 0ull, acc2 = 0ull, acc3 = 0ull;
        unsigned long long acc4 = 0ull, acc5 = 0ull, acc6 = 0ull, acc7 = 0ull;
#pragma unroll
        for (int d = 0; d < DDIM; d++) {
            unsigned long long xx;
            asm("mov.b64 %0, {%1, %1};" : "=l"(xx) : "f"(xr[d]));
            const ulonglong2* p =
                reinterpret_cast<const ulonglong2*>(&s_emb[d * KCB + k0]);
            ulonglong2 e0 = p[0];
            ulonglong2 e1 = p[1];
            ulonglong2 e2 = p[2];
            ulonglong2 e3 = p[3];
            asm("fma.rn.f32x2 %0, %1, %2, %0;" : "+l"(acc0) : "l"(xx), "l"(e0.x));
            asm("fma.rn.f32x2 %0, %1, %2, %0;" : "+l"(acc1) : "l"(xx), "l"(e0.y));
            asm("fma.rn.f32x2 %0, %1, %2, %0;" : "+l"(acc2) : "l"(xx), "l"(e1.x));
            asm("fma.rn.f32x2 %0, %1, %2, %0;" : "+l"(acc3) : "l"(xx), "l"(e1.y));
            asm("fma.rn.f32x2 %0, %1, %2, %0;" : "+l"(acc4) : "l"(xx), "l"(e2.x));
            asm("fma.rn.f32x2 %0, %1, %2, %0;" : "+l"(acc5) : "l"(xx), "l"(e2.y));
            asm("fma.rn.f32x2 %0, %1, %2, %0;" : "+l"(acc6) : "l"(xx), "l"(e3.x));
            asm("fma.rn.f32x2 %0, %1, %2, %0;" : "+l"(acc7) : "l"(xx), "l"(e3.y));
        }
        unsigned long long accs[8] = {acc0, acc1, acc2, acc3, acc4, acc5, acc6, acc7};
#pragma unroll
        for (int j = 0; j < 8; j++) {
            float lo, hi;
            asm("mov.b64 {%0, %1}, %2;" : "=f"(lo), "=f"(hi) : "l"(accs[j]));
            int k = k0 + 2 * j;
            float s0 = fmaf(-2.f, lo, s_enorm[k]);
            float s1 = fmaf(-2.f, hi, s_enorm[k + 1]);
            if (s0 < best) { best = s0; bidx = k; }
            if (s1 < best) { best = s1; bidx = k + 1; }
        }
    }

    // Emit index (as float)
    out_idx[row] = (float)bidx;

    // Quantized row (gather column bidx), loss partial, dw scatter
    float lsum = 0.f;
    float* oq = out_q + (size_t)row * DDIM;
#pragma unroll
    for (int d = 0; d < DDIM; d += 4) {
        float q0 = s_emb[(d + 0) * KCB + bidx];
        float q1 = s_emb[(d + 1) * KCB + bidx];
        float q2 = s_emb[(d + 2) * KCB + bidx];
        float q3 = s_emb[(d + 3) * KCB + bidx];
        float4 qv = make_float4(q0, q1, q2, q3);
        *reinterpret_cast<float4*>(oq + d) = qv;
        float d0 = q0 - xr[d + 0];
        float d1 = q1 - xr[d + 1];
        float d2 = q2 - xr[d + 2];
        float d3 = q3 - xr[d + 3];
        lsum = fmaf(d0, d0, lsum);
        lsum = fmaf(d1, d1, lsum);
        lsum = fmaf(d2, d2, lsum);
        lsum = fmaf(d3, d3, lsum);
        atomicAdd(&g_dw[(d + 0) * KCB + bidx], xr[d + 0]);
        atomicAdd(&g_dw[(d + 1) * KCB + bidx], xr[d + 1]);
        atomicAdd(&g_dw[(d + 2) * KCB + bidx], xr[d + 2]);
        atomicAdd(&g_dw[(d + 3) * KCB + bidx], xr[d + 3]);
    }
    atomicAdd(&s_hist[bidx], 1);

    // Warp-reduce loss, one atomic per warp
#pragma unroll
    for (int o = 16; o > 0; o >>= 1)
        lsum += __shfl_xor_sync(0xffffffffu, lsum, o);
    if ((tid & 31) == 0) atomicAdd(&g_loss, lsum);

    __syncthreads();
    if (tid < KCB) {
        int c = s_hist[tid];
        if (c) atomicAdd(&g_cluster[tid], (float)c);
    }
}

// ---------------------------------------------------------------------------
// Finalize: EMA updates, perplexity, loss, new embeddings
// ---------------------------------------------------------------------------
__global__ void k_final(const float* __restrict__ ehc,
                        const float* __restrict__ ehd,
                        const int* __restrict__ counter,
                        float* __restrict__ out) {
    __shared__ float red_n[512];
    __shared__ float red_p[512];

    const int k = threadIdx.x;
    const float decay = 0.99f;
    const float one_minus_decay = 1.0f - 0.99f;

    float cn = g_cluster[k];
    float p  = cn * (1.0f / (float)NROWS);
    float plogp = p * logf(p + 1e-10f);

    float t = (float)(*counter + 1);
    float debias = 1.0f - powf(decay, t);
    float inv_debias = 1.0f / debias;

    float h  = ehc[k];
    float nhc = h - (h - cn) * one_minus_decay;
    float avgc = nhc * inv_debias;

    red_n[k] = avgc;
    red_p[k] = plogp;
    __syncthreads();
#pragma unroll
    for (int s = 256; s > 0; s >>= 1) {
        if (k < s) { red_n[k] += red_n[k + s]; red_p[k] += red_p[k + s]; }
        __syncthreads();
    }
    float n_total = red_n[0];

    float smoothed = (avgc + 1e-5f) / (n_total + (float)KCB * 1e-5f) * n_total;

    float* out_emb = out + OFF_EMB;
#pragma unroll 8
    for (int d = 0; d < DDIM; d++) {
        float dw  = g_dw[d * KCB + k];
        float hd  = ehd[d * KCB + k];
        float nhd = hd - (hd - dw) * one_minus_decay;
        out_emb[d * KCB + k] = (nhd * inv_debias) / smoothed;
    }

    if (k == 0) {
        out[OFF_LOSS] = 0.25f * g_loss / (float)((size_t)NROWS * DDIM);
        out[OFF_PERP] = expf(-red_p[0]);
    }
}

// ---------------------------------------------------------------------------
extern "C" void kernel_launch(void* const* d_in, const int* in_sizes, int n_in,
                              void* d_out, int out_size) {
    const float* x       = (const float*)d_in[0];
    const float* emb     = (const float*)d_in[1];
    const float* ehc     = (const float*)d_in[2];
    const float* ehd     = (const float*)d_in[3];
    const int*   counter = (const int*)d_in[4];
    float* out = (float*)d_out;

    size_t smem = (size_t)(DDIM * KCB + KCB) * sizeof(float) + KCB * sizeof(int);
    cudaFuncSetAttribute(k_main, cudaFuncAttributeMaxDynamicSharedMemorySize, (int)smem);

    k_init<<<64, 512>>>(emb);
    k_main<<<NROWS / 512, 512, smem>>>(x, emb, out + OFF_Q, out + OFF_IDX);
    k_final<<<1, 512>>>(ehc, ehd, counter, out);
}

// round 3
// speedup vs baseline: 1.8368x; 1.8368x over previous
#include <cuda_runtime.h>
#include <cuda_bf16.h>
#include <cstdint>
#include <math.h>

#define NROWS 131072
#define DDIM  64
#define KCB   512
#define TILE_M 128
#define NTILES (NROWS / TILE_M)    // 1024
#define GRID_MAIN 148

// Output layout (float32): q[NROWS*64], loss, perp, new_emb[64*512], idx[NROWS]
#define OFF_Q    0
#define OFF_LOSS (NROWS * DDIM)
#define OFF_PERP (OFF_LOSS + 1)
#define OFF_EMB  (OFF_PERP + 1)
#define OFF_IDX  (OFF_EMB + DDIM * KCB)

// margin (on squared distance) below which we re-check exactly in fp32.
// Worst-case split-bf16 distance error ~8e-3; margin 0.03125 >> 2x that.
#define MARGIN_TH 0.03125f

// Device scratch (zero-init at load; re-zeroed by k_final each call)
__device__ float g_dw[DDIM * KCB];
__device__ float g_cluster[KCB];
__device__ float g_loss;
__device__ float g_enorm[KCB];
__device__ int   g_resc_rows[NROWS];
__device__ int   g_resc_n;

// ---------------------------------------------------------------------------
// smem layout (bytes). SW128 swizzle with 128B rows: for byte offset
// o = r*128 + c (c<128), SW128(o) = r*128 + (c ^ ((r&7)*16)).
// ---------------------------------------------------------------------------
#define SO_EHI   0u          // 65536: e_hi bf16 [512 codes][64 dims] 128B rows
#define SO_ELO   65536u      // 65536
#define SO_XHI   131072u     // 16384: x_hi bf16 [128 rows][64 dims]
#define SO_XLO   147456u     // 16384
#define SO_X     163840u     // 33792: x fp32 [128][66] padded
#define SO_EN    197632u     // 2048:  ||e||^2
#define SO_BB    199680u     // 512:   per-row best dist
#define SO_SB    200192u     // 512:   per-row second-best dist
#define SO_BI    200704u     // 512:   per-row argmin (int)
#define SO_HIST  201216u     // 2048:  histogram (int)
#define SMEM_SZ  203264u

__device__ __forceinline__ void mma_bf16(float* d, const uint32_t* a,
                                         const uint32_t* b) {
    asm volatile(
        "mma.sync.aligned.m16n8k16.row.col.f32.bf16.bf16.f32 "
        "{%0,%1,%2,%3}, {%4,%5,%6,%7}, {%8,%9}, {%0,%1,%2,%3};\n"
        : "+f"(d[0]), "+f"(d[1]), "+f"(d[2]), "+f"(d[3])
        : "r"(a[0]), "r"(a[1]), "r"(a[2]), "r"(a[3]), "r"(b[0]), "r"(b[1]));
}

// ---------------------------------------------------------------------------
// Prep: ||e_k||^2
// ---------------------------------------------------------------------------
__global__ void k_prep(const float* __restrict__ emb) {
    int k = threadIdx.x;
    float s = 0.f;
#pragma unroll
    for (int d = 0; d < DDIM; d++) {
        float e = emb[d * KCB + k];
        s = fmaf(e, e, s);
    }
    g_enorm[k] = s;
}

// ---------------------------------------------------------------------------
// Main: persistent split-bf16 HMMA distance GEMM + argmin + emission
// ---------------------------------------------------------------------------
__global__ __launch_bounds__(256, 1)
void k_main(const float* __restrict__ x, const float* __restrict__ emb,
            float* __restrict__ out_q, float* __restrict__ out_idx) {
    extern __shared__ __align__(1024) char sm[];
    const int tid  = threadIdx.x;
    const int wid  = tid >> 5;
    const int lane = tid & 31;
    const int g    = lane >> 2;      // row group within warp tile
    const int q    = lane & 3;       // col quad
    const uint32_t xg = (uint32_t)g * 16;   // swizzle XOR for B rows (n&7 == g)

    float* s_x    = (float*)(sm + SO_X);
    float* s_en   = (float*)(sm + SO_EN);
    float* s_bb   = (float*)(sm + SO_BB);
    float* s_sb   = (float*)(sm + SO_SB);
    int*   s_bi   = (int*)(sm + SO_BI);
    int*   s_hist = (int*)(sm + SO_HIST);

    // ---- Stage embeddings hi/lo (once per persistent CTA) ----
    // emb is [d][k]; storage row = code k, col = dim d (bf16, SW128).
    for (int i = tid; i < DDIM * KCB; i += 256) {
        int d = i >> 9, k = i & 511;
        float e = emb[i];
        __nv_bfloat16 hi = __float2bfloat16(e);
        __nv_bfloat16 lo = __float2bfloat16(e - __bfloat162float(hi));
        uint32_t off = (uint32_t)k * 128 + (((uint32_t)d * 2) ^ ((k & 7) * 16));
        *(__nv_bfloat16*)(sm + SO_EHI + off) = hi;
        *(__nv_bfloat16*)(sm + SO_ELO + off) = lo;
    }
    for (int i = tid; i < KCB; i += 256) s_en[i] = g_enorm[i];
    for (int i = tid; i < KCB; i += 256) s_hist[i] = 0;
    __syncthreads();

    const int r0 = wid * 16 + g;       // warp's row block rows r0, r0+8
    const int r1 = r0 + 8;
    const uint32_t xr = (uint32_t)(r0 & 7) * 16;   // same for r1

    float loss_acc = 0.f;

    for (int tile = blockIdx.x; tile < NTILES; tile += gridDim.x) {
        const float* xt = x + (size_t)tile * TILE_M * DDIM;

        // ---- Stage x tile: fp32 (padded) + hi/lo bf16 (SW128) ----
        for (int i = tid; i < TILE_M * DDIM / 4; i += 256) {
            float4 v = ((const float4*)xt)[i];
            int r = i >> 4, c = (i & 15) * 4;
            s_x[r * 66 + c + 0] = v.x;
            s_x[r * 66 + c + 1] = v.y;
            s_x[r * 66 + c + 2] = v.z;
            s_x[r * 66 + c + 3] = v.w;
            __nv_bfloat16 h0 = __float2bfloat16(v.x), h1 = __float2bfloat16(v.y);
            __nv_bfloat16 h2 = __float2bfloat16(v.z), h3 = __float2bfloat16(v.w);
            __nv_bfloat16 l0 = __float2bfloat16(v.x - __bfloat162float(h0));
            __nv_bfloat16 l1 = __float2bfloat16(v.y - __bfloat162float(h1));
            __nv_bfloat16 l2 = __float2bfloat16(v.z - __bfloat162float(h2));
            __nv_bfloat16 l3 = __float2bfloat16(v.w - __bfloat162float(h3));
            uint32_t o = (uint32_t)r * 128 + (((uint32_t)c * 2) ^ ((r & 7) * 16));
            __nv_bfloat162 p;
            p.x = h0; p.y = h1; *(__nv_bfloat162*)(sm + SO_XHI + o)     = p;
            p.x = h2; p.y = h3; *(__nv_bfloat162*)(sm + SO_XHI + o + 4) = p;
            p.x = l0; p.y = l1; *(__nv_bfloat162*)(sm + SO_XLO + o)     = p;
            p.x = l2; p.y = l3; *(__nv_bfloat162*)(sm + SO_XLO + o + 4) = p;
        }
        __syncthreads();

        // ---- Load A fragments (persist across code blocks) ----
        uint32_t Ahi[4][4], Alo[4][4];
#pragma unroll
        for (int ks = 0; ks < 4; ks++) {
            uint32_t c0 = (uint32_t)(q * 4 + ks * 32);
            uint32_t c1 = c0 + 16;
            uint32_t o00 = (uint32_t)r0 * 128 + (c0 ^ xr);
            uint32_t o10 = (uint32_t)r1 * 128 + (c0 ^ xr);
            uint32_t o01 = (uint32_t)r0 * 128 + (c1 ^ xr);
            uint32_t o11 = (uint32_t)r1 * 128 + (c1 ^ xr);
            Ahi[ks][0] = *(const uint32_t*)(sm + SO_XHI + o00);
            Ahi[ks][1] = *(const uint32_t*)(sm + SO_XHI + o10);
            Ahi[ks][2] = *(const uint32_t*)(sm + SO_XHI + o01);
            Ahi[ks][3] = *(const uint32_t*)(sm + SO_XHI + o11);
            Alo[ks][0] = *(const uint32_t*)(sm + SO_XLO + o00);
            Alo[ks][1] = *(const uint32_t*)(sm + SO_XLO + o10);
            Alo[ks][2] = *(const uint32_t*)(sm + SO_XLO + o01);
            Alo[ks][3] = *(const uint32_t*)(sm + SO_XLO + o11);
        }

        // ---- Distance GEMM + running argmin ----
        float best0 = 3.4e38f, sec0 = 3.4e38f;
        float best1 = 3.4e38f, sec1 = 3.4e38f;
        int   bi0 = 0, bi1 = 0;

#pragma unroll 1
        for (int kb = 0; kb < 8; kb++) {
            float acc[8][4];
#pragma unroll
            for (int nt = 0; nt < 8; nt++)
#pragma unroll
                for (int j = 0; j < 4; j++) acc[nt][j] = 0.f;

#pragma unroll
            for (int nt = 0; nt < 8; nt++) {
                uint32_t ebase = (uint32_t)(kb * 64 + nt * 8 + g) * 128;
#pragma unroll
                for (int ks = 0; ks < 4; ks++) {
                    uint32_t co = (uint32_t)(q * 4 + ks * 32);
                    uint32_t o0 = ebase + (co ^ xg);
                    uint32_t o1 = ebase + ((co + 16) ^ xg);
                    uint32_t bh[2], bl[2];
                    bh[0] = *(const uint32_t*)(sm + SO_EHI + o0);
                    bh[1] = *(const uint32_t*)(sm + SO_EHI + o1);
                    bl[0] = *(const uint32_t*)(sm + SO_ELO + o0);
                    bl[1] = *(const uint32_t*)(sm + SO_ELO + o1);
                    mma_bf16(acc[nt], Ahi[ks], bh);   // x_hi . e_hi
                    mma_bf16(acc[nt], Ahi[ks], bl);   // x_hi . e_lo
                    mma_bf16(acc[nt], Alo[ks], bh);   // x_lo . e_hi
                }
            }
            // distances + best/second update for this 64-code block
#pragma unroll
            for (int nt = 0; nt < 8; nt++) {
                int n0 = kb * 64 + nt * 8 + q * 2;
                float2 en = *(const float2*)&s_en[n0];
                float d0 = fmaf(-2.f, acc[nt][0], en.x);
                float d1 = fmaf(-2.f, acc[nt][1], en.y);
                float d2 = fmaf(-2.f, acc[nt][2], en.x);
                float d3 = fmaf(-2.f, acc[nt][3], en.y);
                if (d0 < best0) { sec0 = best0; best0 = d0; bi0 = n0; }
                else if (d0 < sec0) sec0 = d0;
                if (d1 < best0) { sec0 = best0; best0 = d1; bi0 = n0 + 1; }
                else if (d1 < sec0) sec0 = d1;
                if (d2 < best1) { sec1 = best1; best1 = d2; bi1 = n0; }
                else if (d2 < sec1) sec1 = d2;
                if (d3 < best1) { sec1 = best1; best1 = d3; bi1 = n0 + 1; }
                else if (d3 < sec1) sec1 = d3;
            }
        }

        // ---- Reduce across the 4 quad lanes (same rows, disjoint cols) ----
#pragma unroll
        for (int o = 1; o <= 2; o <<= 1) {
            float ob = __shfl_xor_sync(0xffffffffu, best0, o);
            float os = __shfl_xor_sync(0xffffffffu, sec0, o);
            int   oi = __shfl_xor_sync(0xffffffffu, bi0, o);
            if (ob < best0) { sec0 = fminf(best0, os); best0 = ob; bi0 = oi; }
            else            { sec0 = fminf(sec0, ob); }
            ob = __shfl_xor_sync(0xffffffffu, best1, o);
            os = __shfl_xor_sync(0xffffffffu, sec1, o);
            oi = __shfl_xor_sync(0xffffffffu, bi1, o);
            if (ob < best1) { sec1 = fminf(best1, os); best1 = ob; bi1 = oi; }
            else            { sec1 = fminf(sec1, ob); }
        }
        if (q == 0) {
            s_bb[r0] = best0; s_sb[r0] = sec0; s_bi[r0] = bi0;
            s_bb[r1] = best1; s_sb[r1] = sec1; s_bi[r1] = bi1;
        }
        __syncthreads();

        // ---- Emission: 2 threads per row, 32 dims each ----
        {
            const int rloc  = tid >> 1;
            const int dbase = (tid & 1) * 32;
            const int row   = tile * TILE_M + rloc;
            float bb = s_bb[rloc], sb = s_sb[rloc];
            int   bidx = s_bi[rloc];
            if (sb - bb < MARGIN_TH) {
                if (dbase == 0) {
                    int pos = atomicAdd(&g_resc_n, 1);
                    g_resc_rows[pos] = row;
                }
            } else {
                if (dbase == 0) {
                    out_idx[row] = (float)bidx;
                    atomicAdd(&s_hist[bidx], 1);
                }
                float* oq = out_q + (size_t)row * DDIM;
                uint32_t ebase = (uint32_t)bidx * 128;
                uint32_t xe = (uint32_t)(bidx & 7) * 16;
#pragma unroll
                for (int d = dbase; d < dbase + 32; d += 4) {
                    uint32_t o = ebase + (((uint32_t)d * 2) ^ xe);
                    __nv_bfloat162 h01 = *(__nv_bfloat162*)(sm + SO_EHI + o);
                    __nv_bfloat162 h23 = *(__nv_bfloat162*)(sm + SO_EHI + o + 4);
                    __nv_bfloat162 l01 = *(__nv_bfloat162*)(sm + SO_ELO + o);
                    __nv_bfloat162 l23 = *(__nv_bfloat162*)(sm + SO_ELO + o + 4);
                    float q0 = __bfloat162float(h01.x) + __bfloat162float(l01.x);
                    float q1 = __bfloat162float(h01.y) + __bfloat162float(l01.y);
                    float q2 = __bfloat162float(h23.x) + __bfloat162float(l23.x);
                    float q3 = __bfloat162float(h23.y) + __bfloat162float(l23.y);
                    *reinterpret_cast<float4*>(oq + d) = make_float4(q0, q1, q2, q3);
                    float x0 = s_x[rloc * 66 + d + 0];
                    float x1 = s_x[rloc * 66 + d + 1];
                    float x2 = s_x[rloc * 66 + d + 2];
                    float x3 = s_x[rloc * 66 + d + 3];
                    float f0 = q0 - x0, f1 = q1 - x1, f2 = q2 - x2, f3 = q3 - x3;
                    loss_acc = fmaf(f0, f0, loss_acc);
                    loss_acc = fmaf(f1, f1, loss_acc);
                    loss_acc = fmaf(f2, f2, loss_acc);
                    loss_acc = fmaf(f3, f3, loss_acc);
                    atomicAdd(&g_dw[(d + 0) * KCB + bidx], x0);
                    atomicAdd(&g_dw[(d + 1) * KCB + bidx], x1);
                    atomicAdd(&g_dw[(d + 2) * KCB + bidx], x2);
                    atomicAdd(&g_dw[(d + 3) * KCB + bidx], x3);
                }
            }
        }
        __syncthreads();   // protect s_x / x tiles / s_bb before next tile
    }

    // ---- Loss: one atomic per warp ----
#pragma unroll
    for (int o = 16; o > 0; o >>= 1)
        loss_acc += __shfl_xor_sync(0xffffffffu, loss_acc, o);
    if (lane == 0) atomicAdd(&g_loss, loss_acc);

    // ---- Histogram merge ----
    for (int i = tid; i < KCB; i += 256) {
        int c = s_hist[i];
        if (c) atomicAdd(&g_cluster[i], (float)c);
    }
}

// ---------------------------------------------------------------------------
// Rescue: exact fp32 re-scan for flagged rows (warp per row)
// ---------------------------------------------------------------------------
__global__ __launch_bounds__(128)
void k_rescue(const float* __restrict__ x, const float* __restrict__ emb,
              float* __restrict__ out_q, float* __restrict__ out_idx) {
    const int n = g_resc_n;
    const int lane = threadIdx.x & 31;
    const int gw = blockIdx.x * 4 + (threadIdx.x >> 5);
    for (int i = gw; i < n; i += gridDim.x * 4) {
        const int row = g_resc_rows[i];
        const float* xr = x + (size_t)row * DDIM;
        float best = 3.4e38f;
        int bidx = 1 << 30;
#pragma unroll 1
        for (int kb = 0; kb < 16; kb++) {
            int k = kb * 32 + lane;
            float dot = 0.f;
#pragma unroll
            for (int d = 0; d < DDIM; d++)
                dot = fmaf(__ldg(xr + d), __ldg(emb + d * KCB + k), dot);
            float dist = fmaf(-2.f, dot, g_enorm[k]);
            if (dist < best) { best = dist; bidx = k; }
        }
#pragma unroll
        for (int o = 16; o > 0; o >>= 1) {
            float ob = __shfl_xor_sync(0xffffffffu, best, o);
            int   oi = __shfl_xor_sync(0xffffffffu, bidx, o);
            if (ob < best || (ob == best && oi < bidx)) { best = ob; bidx = oi; }
        }
        float lsum = 0.f;
#pragma unroll
        for (int d = lane; d < DDIM; d += 32) {
            float qv = emb[d * KCB + bidx];
            float xv = xr[d];
            out_q[(size_t)row * DDIM + d] = qv;
            float df = qv - xv;
            lsum = fmaf(df, df, lsum);
            atomicAdd(&g_dw[d * KCB + bidx], xv);
        }
#pragma unroll
        for (int o = 16; o > 0; o >>= 1)
            lsum += __shfl_xor_sync(0xffffffffu, lsum, o);
        if (lane == 0) {
            out_idx[row] = (float)bidx;
            atomicAdd(&g_cluster[bidx], 1.f);
            atomicAdd(&g_loss, lsum);
        }
    }
}

// ---------------------------------------------------------------------------
// Finalize: EMA updates, perplexity, loss; re-zero scratch for next call
// ---------------------------------------------------------------------------
__global__ void k_final(const float* __restrict__ ehc,
                        const float* __restrict__ ehd,
                        const int* __restrict__ counter,
                        float* __restrict__ out) {
    __shared__ float red_n[512];
    __shared__ float red_p[512];

    const int k = threadIdx.x;
    const float one_minus_decay = 0.01f;

    float cn = g_cluster[k];
    float p  = cn * (1.0f / (float)NROWS);
    float plogp = p * logf(p + 1e-10f);

    float t = (float)(*counter + 1);
    float debias = 1.0f - powf(0.99f, t);
    float inv_debias = 1.0f / debias;

    float h    = ehc[k];
    float nhc  = h - (h - cn) * one_minus_decay;
    float avgc = nhc * inv_debias;

    red_n[k] = avgc;
    red_p[k] = plogp;
    __syncthreads();
#pragma unroll
    for (int s = 256; s > 0; s >>= 1) {
        if (k < s) { red_n[k] += red_n[k + s]; red_p[k] += red_p[k + s]; }
        __syncthreads();
    }
    float n_total = red_n[0];
    float smoothed = (avgc + 1e-5f) / (n_total + (float)KCB * 1e-5f) * n_total;

    float* out_emb = out + OFF_EMB;
#pragma unroll 8
    for (int d = 0; d < DDIM; d++) {
        float dw  = g_dw[d * KCB + k];
        float hd  = ehd[d * KCB + k];
        float nhd = hd - (hd - dw) * one_minus_decay;
        out_emb[d * KCB + k] = (nhd * inv_debias) / smoothed;
        g_dw[d * KCB + k] = 0.f;
    }
    g_cluster[k] = 0.f;
    if (k == 0) {
        out[OFF_LOSS] = 0.25f * g_loss / (float)((size_t)NROWS * DDIM);
        out[OFF_PERP] = expf(-red_p[0]);
        g_loss = 0.f;
        g_resc_n = 0;
    }
}

// ---------------------------------------------------------------------------
extern "C" void kernel_launch(void* const* d_in, const int* in_sizes, int n_in,
                              void* d_out, int out_size) {
    const float* x       = (const float*)d_in[0];
    const float* emb     = (const float*)d_in[1];
    const float* ehc     = (const float*)d_in[2];
    const float* ehd     = (const float*)d_in[3];
    const int*   counter = (const int*)d_in[4];
    float* out = (float*)d_out;

    cudaFuncSetAttribute(k_main, cudaFuncAttributeMaxDynamicSharedMemorySize,
                         (int)SMEM_SZ);

    k_prep<<<1, 512>>>(emb);
    k_main<<<GRID_MAIN, 256, SMEM_SZ>>>(x, emb, out + OFF_Q, out + OFF_IDX);
    k_rescue<<<GRID_MAIN, 128>>>(x, emb, out + OFF_Q, out + OFF_IDX);
    k_final<<<1, 512>>>(ehc, ehd, counter, out);
}

// round 4
// speedup vs baseline: 2.0340x; 1.1074x over previous
#include <cuda_runtime.h>
#include <cuda_fp16.h>
#include <cstdint>
#include <math.h>

#define NROWS 131072
#define DDIM  64
#define KCB   512
#define TILE_M 128
#define NTILES (NROWS / TILE_M)    // 1024
#define GRID_MAIN 148

// Output layout (float32): q[NROWS*64], loss, perp, new_emb[64*512], idx[NROWS]
#define OFF_Q    0
#define OFF_LOSS (NROWS * DDIM)
#define OFF_PERP (OFF_LOSS + 1)
#define OFF_EMB  (OFF_PERP + 1)
#define OFF_IDX  (OFF_EMB + DDIM * KCB)

// Rescue margin on squared distance. fp16 single-pass distance-diff error:
// hard bound ~0.3, sigma ~0.007 -> 0.15 is ~21 sigma; rescue ~1.6% of rows.
#define MARGIN_TH 0.15f

// Device scratch (zero-init at load; k_prep re-zeroes accumulators each call)
__device__ float g_dw[DDIM * KCB];
__device__ float g_cluster[KCB];
__device__ float g_loss;
__device__ float g_enorm[KCB];
__device__ int   g_resc_rows[NROWS];
__device__ int   g_resc_n;

// ---------------------------------------------------------------------------
// Packed smem layout for MMA operands.
// Each 128B row holds 64 fp16 dims of one code/x-row, permuted so lane (g,q)
// reads its whole m16n8k16 fragment (all 4 k-steps) as two contiguous LDS.128:
//   byte(d) = ((d>>1)&3)*32 + (d>>4)*8 + ((d>>3)&1)*4 + (d&1)*2
// Physical addr = row*128 + (byte ^ ((row&7)*16))   (conflict-free swizzle)
// ---------------------------------------------------------------------------
__device__ __forceinline__ uint32_t pb(uint32_t d) {
    return ((d >> 1) & 3u) * 32u + (d >> 4) * 8u + ((d >> 3) & 1u) * 4u + (d & 1u) * 2u;
}

#define SO_EH    0u          // 65536: e fp16 hi, packed
#define SO_EL    65536u      // 65536: e fp16 residual, packed (emission only)
#define SO_XH    131072u     // 16384: x fp16, packed
#define SO_X     147456u     // 33792: x fp32 [128][66] padded
#define SO_EN    181248u     // 2048
#define SO_BB    183296u     // 512
#define SO_SB    183808u     // 512
#define SO_BI    184320u     // 512
#define SO_HIST  184832u     // 2048
#define SMEM_SZ  186880u

__device__ __forceinline__ void mma_f16(float* d, uint32_t a0, uint32_t a1,
                                        uint32_t a2, uint32_t a3,
                                        uint32_t b0, uint32_t b1) {
    asm volatile(
        "mma.sync.aligned.m16n8k16.row.col.f32.f16.f16.f32 "
        "{%0,%1,%2,%3}, {%4,%5,%6,%7}, {%8,%9}, {%0,%1,%2,%3};\n"
        : "+f"(d[0]), "+f"(d[1]), "+f"(d[2]), "+f"(d[3])
        : "r"(a0), "r"(a1), "r"(a2), "r"(a3), "r"(b0), "r"(b1));
}

// ---------------------------------------------------------------------------
// Prep: exact ||e_k||^2 (deterministic reduce) + zero all accumulators
// grid 8 x 512
// ---------------------------------------------------------------------------
__global__ void k_prep(const float* __restrict__ emb) {
    __shared__ float red[8][64];
    const int t = threadIdx.x;
    const int b = blockIdx.x;
    const int kk = t & 63;
    const int part = t >> 6;
    const int k = b * 64 + kk;
    float s = 0.f;
#pragma unroll
    for (int j = 0; j < 8; j++) {
        float e = emb[(part * 8 + j) * KCB + k];
        s = fmaf(e, e, s);
    }
    red[part][kk] = s;
    __syncthreads();
    if (t < 64) {
        float tot = red[0][t];
#pragma unroll
        for (int p = 1; p < 8; p++) tot += red[p][t];
        g_enorm[b * 64 + t] = tot;
    }
    // zero accumulators for this call
#pragma unroll
    for (int i = 0; i < 8; i++) g_dw[b * 512 + t + i * 4096] = 0.f;
    if (b == 0) {
        g_cluster[t] = 0.f;
        if (t == 0) { g_loss = 0.f; g_resc_n = 0; }
    }
}

// ---------------------------------------------------------------------------
// Main: persistent single-pass fp16 HMMA distance GEMM + argmin + emission
// ---------------------------------------------------------------------------
__global__ __launch_bounds__(256, 1)
void k_main(const float* __restrict__ x, const float* __restrict__ emb,
            float* __restrict__ out_q, float* __restrict__ out_idx) {
    extern __shared__ __align__(1024) char sm[];
    const int tid  = threadIdx.x;
    const int wid  = tid >> 5;
    const int lane = tid & 31;
    const int g    = lane >> 2;
    const int q    = lane & 3;

    float* s_x    = (float*)(sm + SO_X);
    float* s_en   = (float*)(sm + SO_EN);
    float* s_bb   = (float*)(sm + SO_BB);
    float* s_sb   = (float*)(sm + SO_SB);
    int*   s_bi   = (int*)(sm + SO_BI);
    int*   s_hist = (int*)(sm + SO_HIST);

    // ---- Stage embeddings (fp16 hi + residual), packed layout ----
    for (int i = tid; i < DDIM * KCB; i += 256) {
        uint32_t d = (uint32_t)i >> 9, k = (uint32_t)i & 511u;
        float e = emb[i];
        __half h = __float2half_rn(e);
        __half l = __float2half_rn(e - __half2float(h));
        uint32_t off = k * 128u + (pb(d) ^ ((k & 7u) * 16u));
        *(__half*)(sm + SO_EH + off) = h;
        *(__half*)(sm + SO_EL + off) = l;
    }
    for (int i = tid; i < KCB; i += 256) { s_en[i] = g_enorm[i]; s_hist[i] = 0; }
    __syncthreads();

    const int r0 = wid * 16 + g;          // rows r0, r0+8 for this lane group
    const int r1 = r0 + 8;
    const uint32_t c0 = ((uint32_t)q * 32u) ^ ((uint32_t)g * 16u);
    const uint32_t c1 = ((uint32_t)q * 32u + 16u) ^ ((uint32_t)g * 16u);

    float loss_acc = 0.f;

    for (int tile = blockIdx.x; tile < NTILES; tile += gridDim.x) {
        const float* xt = x + (size_t)tile * TILE_M * DDIM;

        // ---- Stage x tile: fp32 (padded) + fp16 packed ----
        for (int i = tid; i < TILE_M * DDIM / 4; i += 256) {
            float4 v = ((const float4*)xt)[i];
            uint32_t r = (uint32_t)i >> 4, c = ((uint32_t)i & 15u) * 4u;
            *(float2*)&s_x[r * 66 + c]     = make_float2(v.x, v.y);
            *(float2*)&s_x[r * 66 + c + 2] = make_float2(v.z, v.w);
            uint32_t xw = (r & 7u) * 16u;
            *(__half2*)(sm + SO_XH + r * 128u + (pb(c) ^ xw)) =
                __floats2half2_rn(v.x, v.y);
            *(__half2*)(sm + SO_XH + r * 128u + (pb(c + 2) ^ xw)) =
                __floats2half2_rn(v.z, v.w);
        }
        __syncthreads();

        // ---- A fragments: 4 LDS.128, all 4 k-steps ----
        uint4 A0a = *(const uint4*)(sm + SO_XH + (uint32_t)r0 * 128u + c0);
        uint4 A0b = *(const uint4*)(sm + SO_XH + (uint32_t)r0 * 128u + c1);
        uint4 A1a = *(const uint4*)(sm + SO_XH + (uint32_t)r1 * 128u + c0);
        uint4 A1b = *(const uint4*)(sm + SO_XH + (uint32_t)r1 * 128u + c1);

        // ---- Distance GEMM + running argmin ----
        float best0 = 3.4e38f, sec0 = 3.4e38f;
        float best1 = 3.4e38f, sec1 = 3.4e38f;
        int   bi0 = 0, bi1 = 0;

#pragma unroll 1
        for (int kb = 0; kb < 8; kb++) {
            float acc[8][4];
#pragma unroll
            for (int nt = 0; nt < 8; nt++)
#pragma unroll
                for (int j = 0; j < 4; j++) acc[nt][j] = 0.f;

#pragma unroll
            for (int nt = 0; nt < 8; nt++) {
                uint32_t rowb = (uint32_t)(kb * 64 + nt * 8 + g) * 128u;
                uint4 B0 = *(const uint4*)(sm + SO_EH + rowb + c0);
                uint4 B1 = *(const uint4*)(sm + SO_EH + rowb + c1);
                mma_f16(acc[nt], A0a.x, A1a.x, A0a.y, A1a.y, B0.x, B0.y); // ks0
                mma_f16(acc[nt], A0a.z, A1a.z, A0a.w, A1a.w, B0.z, B0.w); // ks1
                mma_f16(acc[nt], A0b.x, A1b.x, A0b.y, A1b.y, B1.x, B1.y); // ks2
                mma_f16(acc[nt], A0b.z, A1b.z, A0b.w, A1b.w, B1.z, B1.w); // ks3
            }
#pragma unroll
            for (int nt = 0; nt < 8; nt++) {
                int n0 = kb * 64 + nt * 8 + q * 2;
                float2 en = *(const float2*)&s_en[n0];
                float d0 = fmaf(-2.f, acc[nt][0], en.x);
                float d1 = fmaf(-2.f, acc[nt][1], en.y);
                float d2 = fmaf(-2.f, acc[nt][2], en.x);
                float d3 = fmaf(-2.f, acc[nt][3], en.y);
                if (d0 < best0) { sec0 = best0; best0 = d0; bi0 = n0; }
                else if (d0 < sec0) sec0 = d0;
                if (d1 < best0) { sec0 = best0; best0 = d1; bi0 = n0 + 1; }
                else if (d1 < sec0) sec0 = d1;
                if (d2 < best1) { sec1 = best1; best1 = d2; bi1 = n0; }
                else if (d2 < sec1) sec1 = d2;
                if (d3 < best1) { sec1 = best1; best1 = d3; bi1 = n0 + 1; }
                else if (d3 < sec1) sec1 = d3;
            }
        }

        // ---- Merge across the 4 quad lanes ----
#pragma unroll
        for (int o = 1; o <= 2; o <<= 1) {
            float ob = __shfl_xor_sync(0xffffffffu, best0, o);
            float os = __shfl_xor_sync(0xffffffffu, sec0, o);
            int   oi = __shfl_xor_sync(0xffffffffu, bi0, o);
            if (ob < best0) { sec0 = fminf(best0, os); best0 = ob; bi0 = oi; }
            else            { sec0 = fminf(sec0, ob); }
            ob = __shfl_xor_sync(0xffffffffu, best1, o);
            os = __shfl_xor_sync(0xffffffffu, sec1, o);
            oi = __shfl_xor_sync(0xffffffffu, bi1, o);
            if (ob < best1) { sec1 = fminf(best1, os); best1 = ob; bi1 = oi; }
            else            { sec1 = fminf(sec1, ob); }
        }
        if (q == 0) {
            s_bb[r0] = best0; s_sb[r0] = sec0; s_bi[r0] = bi0;
            s_bb[r1] = best1; s_sb[r1] = sec1; s_bi[r1] = bi1;
        }
        __syncthreads();

        // ---- Emission: 2 threads per row, 32 dims each ----
        {
            const int rloc  = tid >> 1;
            const int dbase = (tid & 1) * 32;
            const int row   = tile * TILE_M + rloc;
            float bb = s_bb[rloc], sb = s_sb[rloc];
            int   bidx = s_bi[rloc];
            if (sb - bb < MARGIN_TH) {
                if (dbase == 0) {
                    int pos = atomicAdd(&g_resc_n, 1);
                    g_resc_rows[pos] = row;
                }
            } else {
                if (dbase == 0) {
                    out_idx[row] = (float)bidx;
                    atomicAdd(&s_hist[bidx], 1);
                }
                float* oq = out_q + (size_t)row * DDIM;
                uint32_t ebase = (uint32_t)bidx * 128u;
                uint32_t xe = ((uint32_t)bidx & 7u) * 16u;
#pragma unroll
                for (int d = dbase; d < dbase + 32; d += 4) {
                    uint32_t oA = ebase + (pb((uint32_t)d) ^ xe);
                    uint32_t oB = ebase + (pb((uint32_t)d + 2) ^ xe);
                    __half2 h01 = *(__half2*)(sm + SO_EH + oA);
                    __half2 h23 = *(__half2*)(sm + SO_EH + oB);
                    __half2 l01 = *(__half2*)(sm + SO_EL + oA);
                    __half2 l23 = *(__half2*)(sm + SO_EL + oB);
                    float q0 = __half2float(h01.x) + __half2float(l01.x);
                    float q1 = __half2float(h01.y) + __half2float(l01.y);
                    float q2 = __half2float(h23.x) + __half2float(l23.x);
                    float q3 = __half2float(h23.y) + __half2float(l23.y);
                    *reinterpret_cast<float4*>(oq + d) = make_float4(q0, q1, q2, q3);
                    float x0 = s_x[rloc * 66 + d + 0];
                    float x1 = s_x[rloc * 66 + d + 1];
                    float x2 = s_x[rloc * 66 + d + 2];
                    float x3 = s_x[rloc * 66 + d + 3];
                    float f0 = q0 - x0, f1 = q1 - x1, f2 = q2 - x2, f3 = q3 - x3;
                    loss_acc = fmaf(f0, f0, loss_acc);
                    loss_acc = fmaf(f1, f1, loss_acc);
                    loss_acc = fmaf(f2, f2, loss_acc);
                    loss_acc = fmaf(f3, f3, loss_acc);
                    atomicAdd(&g_dw[(d + 0) * KCB + bidx], x0);
                    atomicAdd(&g_dw[(d + 1) * KCB + bidx], x1);
                    atomicAdd(&g_dw[(d + 2) * KCB + bidx], x2);
                    atomicAdd(&g_dw[(d + 3) * KCB + bidx], x3);
                }
            }
        }
        __syncthreads();
    }

    // ---- Loss: one atomic per warp ----
#pragma unroll
    for (int o = 16; o > 0; o >>= 1)
        loss_acc += __shfl_xor_sync(0xffffffffu, loss_acc, o);
    if (lane == 0) atomicAdd(&g_loss, loss_acc);

    // ---- Histogram merge ----
    for (int i = tid; i < KCB; i += 256) {
        int c = s_hist[i];
        if (c) atomicAdd(&g_cluster[i], (float)c);
    }
}

// ---------------------------------------------------------------------------
// Rescue: exact fp32 re-scan for flagged rows (warp per row)
// ---------------------------------------------------------------------------
__global__ __launch_bounds__(128)
void k_rescue(const float* __restrict__ x, const float* __restrict__ emb,
              float* __restrict__ out_q, float* __restrict__ out_idx) {
    const int n = g_resc_n;
    const int lane = threadIdx.x & 31;
    const int gw = blockIdx.x * 4 + (threadIdx.x >> 5);
    for (int i = gw; i < n; i += gridDim.x * 4) {
        const int row = g_resc_rows[i];
        const float* xr = x + (size_t)row * DDIM;
        float best = 3.4e38f;
        int bidx = 1 << 30;
#pragma unroll 1
        for (int kb = 0; kb < 16; kb++) {
            int k = kb * 32 + lane;
            float dot = 0.f;
#pragma unroll
            for (int d = 0; d < DDIM; d++)
                dot = fmaf(__ldg(xr + d), __ldg(emb + d * KCB + k), dot);
            float dist = fmaf(-2.f, dot, g_enorm[k]);
            if (dist < best) { best = dist; bidx = k; }
        }
#pragma unroll
        for (int o = 16; o > 0; o >>= 1) {
            float ob = __shfl_xor_sync(0xffffffffu, best, o);
            int   oi = __shfl_xor_sync(0xffffffffu, bidx, o);
            if (ob < best || (ob == best && oi < bidx)) { best = ob; bidx = oi; }
        }
        float lsum = 0.f;
#pragma unroll
        for (int d = lane; d < DDIM; d += 32) {
            float qv = emb[d * KCB + bidx];
            float xv = xr[d];
            out_q[(size_t)row * DDIM + d] = qv;
            float df = qv - xv;
            lsum = fmaf(df, df, lsum);
            atomicAdd(&g_dw[d * KCB + bidx], xv);
        }
#pragma unroll
        for (int o = 16; o > 0; o >>= 1)
            lsum += __shfl_xor_sync(0xffffffffu, lsum, o);
        if (lane == 0) {
            out_idx[row] = (float)bidx;
            atomicAdd(&g_cluster[bidx], 1.f);
            atomicAdd(&g_loss, lsum);
        }
    }
}

// ---------------------------------------------------------------------------
// Finalize: grid 64 x 512. Every block redundantly reduces n_total
// (deterministic tree); block b writes embedding row d=b; block 0 writes
// loss/perplexity.
// ---------------------------------------------------------------------------
__global__ void k_final(const float* __restrict__ ehc,
                        const float* __restrict__ ehd,
                        const int* __restrict__ counter,
                        float* __restrict__ out) {
    __shared__ float red_n[512];
    __shared__ float red_p[512];

    const int k = threadIdx.x;
    const int d = blockIdx.x;
    const float one_minus_decay = 0.01f;

    float cn = g_cluster[k];
    float t = (float)(*counter + 1);
    float debias = 1.0f - powf(0.99f, t);
    float inv_debias = 1.0f / debias;

    float h    = ehc[k];
    float nhc  = h - (h - cn) * one_minus_decay;
    float avgc = nhc * inv_debias;

    red_n[k] = avgc;
    red_p[k] = (d == 0) ? ({ float p = cn * (1.0f / (float)NROWS);
                             p * logf(p + 1e-10f); }) : 0.f;
    __syncthreads();
#pragma unroll
    for (int s = 256; s > 0; s >>= 1) {
        if (k < s) { red_n[k] += red_n[k + s]; red_p[k] += red_p[k + s]; }
        __syncthreads();
    }
    float n_total = red_n[0];
    float smoothed = (avgc + 1e-5f) / (n_total + (float)KCB * 1e-5f) * n_total;

    float dw  = g_dw[d * KCB + k];
    float hd  = ehd[d * KCB + k];
    float nhd = hd - (hd - dw) * one_minus_decay;
    out[OFF_EMB + d * KCB + k] = (nhd * inv_debias) / smoothed;

    if (d == 0 && k == 0) {
        out[OFF_LOSS] = 0.25f * g_loss / (float)((size_t)NROWS * DDIM);
        out[OFF_PERP] = expf(-red_p[0]);
    }
}

// ---------------------------------------------------------------------------
extern "C" void kernel_launch(void* const* d_in, const int* in_sizes, int n_in,
                              void* d_out, int out_size) {
    const float* x       = (const float*)d_in[0];
    const float* emb     = (const float*)d_in[1];
    const float* ehc     = (const float*)d_in[2];
    const float* ehd     = (const float*)d_in[3];
    const int*   counter = (const int*)d_in[4];
    float* out = (float*)d_out;

    cudaFuncSetAttribute(k_main, cudaFuncAttributeMaxDynamicSharedMemorySize,
                         (int)SMEM_SZ);

    k_prep<<<8, 512>>>(emb);
    k_main<<<GRID_MAIN, 256, SMEM_SZ>>>(x, emb, out + OFF_Q, out + OFF_IDX);
    k_rescue<<<GRID_MAIN, 128>>>(x, emb, out + OFF_Q, out + OFF_IDX);
    k_final<<<64, 512>>>(ehc, ehd, counter, out);
}

// round 6
// speedup vs baseline: 2.5274x; 1.2426x over previous
#include <cuda_runtime.h>
#include <cuda_fp16.h>
#include <cstdint>
#include <math.h>

#define NROWS 131072
#define DDIM  64
#define KCB   512
#define TILE_M 128
#define NTILES (NROWS / TILE_M)
#define GRID_MAIN 148

// Output layout (float32): q[NROWS*64], loss, perp, new_emb[64*512], idx[NROWS]
#define OFF_Q    0
#define OFF_LOSS (NROWS * DDIM)
#define OFF_PERP (OFF_LOSS + 1)
#define OFF_EMB  (OFF_PERP + 1)
#define OFF_IDX  (OFF_EMB + DDIM * KCB)

// Margin on (truncated-key) squared-distance gaps: covers 2x fp16 error
// (~0.09 at 6 sigma) + 2x 9-bit key truncation (<=0.032).
#define MARGIN 0.1875f
#define MASKH  0xFFFFFE00u
// Key bias: key = ||e||^2 - 2 x.e + KEYBIAS must be strictly positive for ALL
// rows/codes so uint ordering == float ordering. ||e||^2 - 2x.e >= -||x||^2
// >= -150 over 131k chi^2_64 draws; 256 gives >100 of slack (incl fp16 err).
#define KEYBIAS 256.0f

// Device scratch
__device__ float g_dw[DDIM * KCB];
__device__ float g_cluster[KCB];
__device__ float g_loss;
__device__ float g_enorm[KCB];

// ---------------------------------------------------------------------------
// Packed smem layout: row*128 + (pb(d) ^ ((row&7)*16)); pb packs fragments so
// a lane reads all 4 k-steps as two LDS.128.
// ---------------------------------------------------------------------------
__device__ __forceinline__ uint32_t pb(uint32_t d) {
    return ((d >> 1) & 3u) * 32u + (d >> 4) * 8u + ((d >> 3) & 1u) * 4u + (d & 1u) * 2u;
}

#define SO_EH    0u          // 65536: e fp16 hi
#define SO_EL    65536u      // 65536: e fp16 residual
#define SO_XH    131072u     // 16384: x fp16
#define SO_X     147456u     // 33792: x fp32 [128][66]
#define SO_EN2   181248u     // 2048:  ||e||^2 + KEYBIAS
#define SO_TOP   183296u     // 2048:  per-row top4 keys (uint4)
#define SO_HIST  185344u     // 2048
#define SO_QUE   187392u     // 512
#define SO_QN    187904u     // 4
#define SO_B64   187912u     // 8
#define SMEM_SZ  187968u

__device__ __forceinline__ void mma_f16(float* d, uint32_t a0, uint32_t a1,
                                        uint32_t a2, uint32_t a3,
                                        uint32_t b0, uint32_t b1) {
    asm volatile(
        "mma.sync.aligned.m16n8k16.row.col.f32.f16.f16.f32 "
        "{%0,%1,%2,%3}, {%4,%5,%6,%7}, {%8,%9}, {%0,%1,%2,%3};\n"
        : "+f"(d[0]), "+f"(d[1]), "+f"(d[2]), "+f"(d[3])
        : "r"(a0), "r"(a1), "r"(a2), "r"(a3), "r"(b0), "r"(b1));
}

// Insert key into sorted top-4 (ascending): 7 IMNMX
__device__ __forceinline__ void ins4(uint32_t& m1, uint32_t& m2, uint32_t& m3,
                                     uint32_t& m4, uint32_t k) {
    uint32_t h1 = max(m1, k); m1 = min(m1, k);
    uint32_t h2 = max(m2, h1); m2 = min(m2, h1);
    uint32_t h3 = max(m3, h2); m3 = min(m3, h2);
    m4 = min(m4, h3);
}

// Exact fp32 squared distance row<->code, from smem (x fp32, e = hi+lo fp16).
__device__ __forceinline__ float exact_dist(const char* sm, int rloc, int code) {
    const float* xr = (const float*)(sm + SO_X) + rloc * 66;
    uint32_t ebase = (uint32_t)code * 128u;
    uint32_t xe = ((uint32_t)code & 7u) * 16u;
    float a0 = 0.f, a1 = 0.f, a2 = 0.f, a3 = 0.f;
#pragma unroll 8
    for (int p = 0; p < 32; p++) {      // dim pair (2p, 2p+1)
        uint32_t off = ebase + (((((uint32_t)p & 3u) * 32u) + (((uint32_t)p >> 3) * 8u)
                                + ((((uint32_t)p >> 2) & 1u) * 4u)) ^ xe);
        __half2 h2v = *(const __half2*)(sm + SO_EH + off);
        __half2 l2v = *(const __half2*)(sm + SO_EL + off);
        float2 xv = *(const float2*)&xr[2 * p];
        float e0 = __half2float(h2v.x) + __half2float(l2v.x);
        float e1 = __half2float(h2v.y) + __half2float(l2v.y);
        float t0 = xv.x - e0, t1 = xv.y - e1;
        if (p & 1) { a2 = fmaf(t0, t0, a2); a3 = fmaf(t1, t1, a3); }
        else       { a0 = fmaf(t0, t0, a0); a1 = fmaf(t1, t1, a1); }
    }
    return (a0 + a2) + (a1 + a3);
}

// ---------------------------------------------------------------------------
// Prep: exact ||e_k||^2 + zero small accumulators
// ---------------------------------------------------------------------------
__global__ void k_prep(const float* __restrict__ emb) {
    __shared__ float red[8][64];
    const int t = threadIdx.x, b = blockIdx.x;
    const int kk = t & 63, part = t >> 6;
    const int k = b * 64 + kk;
    float s = 0.f;
#pragma unroll
    for (int j = 0; j < 8; j++) {
        float e = emb[(part * 8 + j) * KCB + k];
        s = fmaf(e, e, s);
    }
    red[part][kk] = s;
    __syncthreads();
    if (t < 64) {
        float tot = red[0][t];
#pragma unroll
        for (int p = 1; p < 8; p++) tot += red[p][t];
        g_enorm[b * 64 + t] = tot;
    }
    if (b == 0) {
        g_cluster[t] = 0.f;
        if (t == 0) g_loss = 0.f;
    }
}

__global__ void k_zero_a() { g_dw[blockIdx.x * 512 + threadIdx.x] = 0.f; }
__global__ void k_zero_b() { g_dw[16384 + blockIdx.x * 512 + threadIdx.x] = 0.f; }

// ---------------------------------------------------------------------------
// Main: fp16 HMMA distances, top-4 keys, in-CTA exact duel/rescan, emission
// ---------------------------------------------------------------------------
__global__ __launch_bounds__(256, 1)
void k_main(const float* __restrict__ x, const float* __restrict__ emb,
            float* __restrict__ out_q, float* __restrict__ out_idx) {
    extern __shared__ __align__(1024) char sm[];
    const int tid  = threadIdx.x;
    const int wid  = tid >> 5;
    const int lane = tid & 31;
    const int g    = lane >> 2;
    const int q    = lane & 3;

    float* s_x    = (float*)(sm + SO_X);
    float* s_en2  = (float*)(sm + SO_EN2);
    uint4* s_top  = (uint4*)(sm + SO_TOP);
    int*   s_hist = (int*)(sm + SO_HIST);
    int*   s_que  = (int*)(sm + SO_QUE);
    int*   s_qn   = (int*)(sm + SO_QN);
    unsigned long long* s_b64 = (unsigned long long*)(sm + SO_B64);

    // ---- Stage embeddings (fp16 hi + residual) ----
    for (int i = tid; i < DDIM * KCB; i += 256) {
        uint32_t d = (uint32_t)i >> 9, k = (uint32_t)i & 511u;
        float e = emb[i];
        __half h = __float2half_rn(e);
        __half l = __float2half_rn(e - __half2float(h));
        uint32_t off = k * 128u + (pb(d) ^ ((k & 7u) * 16u));
        *(__half*)(sm + SO_EH + off) = h;
        *(__half*)(sm + SO_EL + off) = l;
    }
    for (int i = tid; i < KCB; i += 256) {
        s_en2[i] = g_enorm[i] + KEYBIAS;   // bias keeps keys strictly positive
        s_hist[i] = 0;
    }
    __syncthreads();

    const int r0 = wid * 16 + g;
    const int r1 = r0 + 8;
    const uint32_t c0 = ((uint32_t)q * 32u) ^ ((uint32_t)g * 16u);
    const uint32_t c1 = ((uint32_t)q * 32u + 16u) ^ ((uint32_t)g * 16u);

    float loss_acc = 0.f;

    for (int tile = blockIdx.x; tile < NTILES; tile += gridDim.x) {
        const float* xt = x + (size_t)tile * TILE_M * DDIM;

        if (tid == 0) *s_qn = 0;
        // ---- Stage x tile ----
        for (int i = tid; i < TILE_M * DDIM / 4; i += 256) {
            float4 v = ((const float4*)xt)[i];
            uint32_t r = (uint32_t)i >> 4, c = ((uint32_t)i & 15u) * 4u;
            *(float2*)&s_x[r * 66 + c]     = make_float2(v.x, v.y);
            *(float2*)&s_x[r * 66 + c + 2] = make_float2(v.z, v.w);
            uint32_t xw = (r & 7u) * 16u;
            *(__half2*)(sm + SO_XH + r * 128u + (pb(c) ^ xw)) =
                __floats2half2_rn(v.x, v.y);
            *(__half2*)(sm + SO_XH + r * 128u + (pb(c + 2) ^ xw)) =
                __floats2half2_rn(v.z, v.w);
        }
        __syncthreads();

        // ---- A fragments ----
        uint4 A0a = *(const uint4*)(sm + SO_XH + (uint32_t)r0 * 128u + c0);
        uint4 A0b = *(const uint4*)(sm + SO_XH + (uint32_t)r0 * 128u + c1);
        uint4 A1a = *(const uint4*)(sm + SO_XH + (uint32_t)r1 * 128u + c0);
        uint4 A1b = *(const uint4*)(sm + SO_XH + (uint32_t)r1 * 128u + c1);

        // ---- Distance GEMM + top-4 key tracking ----
        uint32_t p11 = 0xFFFFFFFFu, p12 = 0xFFFFFFFFu, p13 = 0xFFFFFFFFu, p14 = 0xFFFFFFFFu;
        uint32_t p21 = 0xFFFFFFFFu, p22 = 0xFFFFFFFFu, p23 = 0xFFFFFFFFu, p24 = 0xFFFFFFFFu;

#pragma unroll 1
        for (int kb = 0; kb < 8; kb++) {
            float acc[8][4];
#pragma unroll
            for (int nt = 0; nt < 8; nt++)
#pragma unroll
                for (int j = 0; j < 4; j++) acc[nt][j] = 0.f;

#pragma unroll
            for (int nt = 0; nt < 8; nt++) {
                uint32_t rowb = (uint32_t)(kb * 64 + nt * 8 + g) * 128u;
                uint4 B0 = *(const uint4*)(sm + SO_EH + rowb + c0);
                uint4 B1 = *(const uint4*)(sm + SO_EH + rowb + c1);
                mma_f16(acc[nt], A0a.x, A1a.x, A0a.y, A1a.y, B0.x, B0.y);
                mma_f16(acc[nt], A0a.z, A1a.z, A0a.w, A1a.w, B0.z, B0.w);
                mma_f16(acc[nt], A0b.x, A1b.x, A0b.y, A1b.y, B1.x, B1.y);
                mma_f16(acc[nt], A0b.z, A1b.z, A0b.w, A1b.w, B1.z, B1.w);
            }
#pragma unroll
            for (int nt = 0; nt < 8; nt++) {
                uint32_t n0 = (uint32_t)(kb * 64 + nt * 8 + q * 2);
                float2 en = *(const float2*)&s_en2[n0];
                uint32_t k0 = (__float_as_uint(fmaf(-2.f, acc[nt][0], en.x)) & MASKH) | n0;
                uint32_t k1 = (__float_as_uint(fmaf(-2.f, acc[nt][1], en.y)) & MASKH) | (n0 + 1);
                uint32_t k2 = (__float_as_uint(fmaf(-2.f, acc[nt][2], en.x)) & MASKH) | n0;
                uint32_t k3 = (__float_as_uint(fmaf(-2.f, acc[nt][3], en.y)) & MASKH) | (n0 + 1);
                ins4(p11, p12, p13, p14, k0);
                ins4(p11, p12, p13, p14, k1);
                ins4(p21, p22, p23, p24, k2);
                ins4(p21, p22, p23, p24, k3);
            }
        }

        // ---- Merge top-4 across quad lanes ----
#pragma unroll
        for (int o = 1; o <= 2; o <<= 1) {
            uint32_t q1 = __shfl_xor_sync(0xffffffffu, p11, o);
            uint32_t q2 = __shfl_xor_sync(0xffffffffu, p12, o);
            uint32_t q3 = __shfl_xor_sync(0xffffffffu, p13, o);
            uint32_t q4 = __shfl_xor_sync(0xffffffffu, p14, o);
            ins4(p11, p12, p13, p14, q1);
            ins4(p11, p12, p13, p14, q2);
            ins4(p11, p12, p13, p14, q3);
            ins4(p11, p12, p13, p14, q4);
            q1 = __shfl_xor_sync(0xffffffffu, p21, o);
            q2 = __shfl_xor_sync(0xffffffffu, p22, o);
            q3 = __shfl_xor_sync(0xffffffffu, p23, o);
            q4 = __shfl_xor_sync(0xffffffffu, p24, o);
            ins4(p21, p22, p23, p24, q1);
            ins4(p21, p22, p23, p24, q2);
            ins4(p21, p22, p23, p24, q3);
            ins4(p21, p22, p23, p24, q4);
        }
        if (q == 0) {
            s_top[r0] = make_uint4(p11, p12, p13, p14);
            s_top[r1] = make_uint4(p21, p22, p23, p24);
        }
        __syncthreads();

        // ---- Resolution + emission: 2 threads per row ----
        {
            const int rloc = tid >> 1;
            const int half = tid & 1;
            const int row  = tile * TILE_M + rloc;
            uint4 K = s_top[rloc];
            float d1 = __uint_as_float(K.x & MASKH);
            float d2 = __uint_as_float(K.y & MASKH);
            float d3 = __uint_as_float(K.z & MASKH);
            float d4 = __uint_as_float(K.w & MASKH);
            int i1 = (int)(K.x & 511u), i2 = (int)(K.y & 511u), i3 = (int)(K.z & 511u);
            int bidx = i1;
            bool emit = true;
            if (d2 - d1 >= MARGIN) {
                // accept i1
            } else if (d3 - d1 >= MARGIN) {
                float e1 = exact_dist(sm, rloc, i1);
                float e2 = exact_dist(sm, rloc, i2);
                if (e2 < e1 || (e2 == e1 && i2 < i1)) bidx = i2;
            } else if (d4 - d1 >= MARGIN) {
                float e1 = exact_dist(sm, rloc, i1);
                float e2 = exact_dist(sm, rloc, i2);
                float e3 = exact_dist(sm, rloc, i3);
                float be = e1;
                if (e2 < be || (e2 == be && i2 < bidx)) { be = e2; bidx = i2; }
                if (e3 < be || (e3 == be && i3 < bidx)) { be = e3; bidx = i3; }
            } else {
                emit = false;
                if (half == 0) {
                    int p = atomicAdd(s_qn, 1);
                    s_que[p] = rloc;
                }
            }
            if (emit) {
                if (half == 0) {
                    out_idx[row] = (float)bidx;
                    atomicAdd(&s_hist[bidx], 1);
                }
                float* oq = out_q + (size_t)row * DDIM;
                uint32_t ebase = (uint32_t)bidx * 128u;
                uint32_t xe = ((uint32_t)bidx & 7u) * 16u;
#pragma unroll
                for (int d = half * 32; d < half * 32 + 32; d += 4) {
                    uint32_t oA = ebase + (pb((uint32_t)d) ^ xe);
                    uint32_t oB = ebase + (pb((uint32_t)d + 2) ^ xe);
                    __half2 h01 = *(__half2*)(sm + SO_EH + oA);
                    __half2 h23 = *(__half2*)(sm + SO_EH + oB);
                    __half2 l01 = *(__half2*)(sm + SO_EL + oA);
                    __half2 l23 = *(__half2*)(sm + SO_EL + oB);
                    float q0 = __half2float(h01.x) + __half2float(l01.x);
                    float q1 = __half2float(h01.y) + __half2float(l01.y);
                    float q2 = __half2float(h23.x) + __half2float(l23.x);
                    float q3 = __half2float(h23.y) + __half2float(l23.y);
                    *reinterpret_cast<float4*>(oq + d) = make_float4(q0, q1, q2, q3);
                    float x0 = s_x[rloc * 66 + d + 0];
                    float x1 = s_x[rloc * 66 + d + 1];
                    float x2 = s_x[rloc * 66 + d + 2];
                    float x3 = s_x[rloc * 66 + d + 3];
                    float f0 = q0 - x0, f1 = q1 - x1, f2 = q2 - x2, f3 = q3 - x3;
                    loss_acc = fmaf(f0, f0, loss_acc);
                    loss_acc = fmaf(f1, f1, loss_acc);
                    loss_acc = fmaf(f2, f2, loss_acc);
                    loss_acc = fmaf(f3, f3, loss_acc);
                }
            }
        }
        __syncthreads();

        // ---- Rare: block-cooperative exact rescan for queued rows ----
        const int qn = *s_qn;
        for (int qi = 0; qi < qn; qi++) {
            if (tid == 0) *s_b64 = 0xFFFFFFFFFFFFFFFFull;
            __syncthreads();
            const int rloc = s_que[qi];
            float da = exact_dist(sm, rloc, tid * 2);
            float db = exact_dist(sm, rloc, tid * 2 + 1);
            unsigned long long ka =
                (((unsigned long long)__float_as_uint(da)) << 32) | (unsigned)(tid * 2);
            unsigned long long kb2 =
                (((unsigned long long)__float_as_uint(db)) << 32) | (unsigned)(tid * 2 + 1);
            unsigned long long loc = min(ka, kb2);
#pragma unroll
            for (int o = 16; o > 0; o >>= 1) {
                unsigned long long ov = __shfl_xor_sync(0xffffffffu, loc, o);
                loc = min(loc, ov);
            }
            if (lane == 0) atomicMin(s_b64, loc);
            __syncthreads();
            const int bidx = (int)(*s_b64 & 511u);
            const int row = tile * TILE_M + rloc;
            if (tid < 32) {
                int d = tid * 2;
                uint32_t ebase = (uint32_t)bidx * 128u;
                uint32_t xe = ((uint32_t)bidx & 7u) * 16u;
                uint32_t off = ebase + (pb((uint32_t)d) ^ xe);
                __half2 h2v = *(__half2*)(sm + SO_EH + off);
                __half2 l2v = *(__half2*)(sm + SO_EL + off);
                float q0 = __half2float(h2v.x) + __half2float(l2v.x);
                float q1 = __half2float(h2v.y) + __half2float(l2v.y);
                *(float2*)(out_q + (size_t)row * DDIM + d) = make_float2(q0, q1);
                float x0 = s_x[rloc * 66 + d], x1 = s_x[rloc * 66 + d + 1];
                float f0 = q0 - x0, f1 = q1 - x1;
                loss_acc = fmaf(f0, f0, loss_acc);
                loss_acc = fmaf(f1, f1, loss_acc);
            }
            if (tid == 0) {
                out_idx[row] = (float)bidx;
                atomicAdd(&s_hist[bidx], 1);
            }
            __syncthreads();
        }
        __syncthreads();
    }

    // ---- Loss: one atomic per warp ----
#pragma unroll
    for (int o = 16; o > 0; o >>= 1)
        loss_acc += __shfl_xor_sync(0xffffffffu, loss_acc, o);
    if (lane == 0) atomicAdd(&g_loss, loss_acc);

    // ---- Histogram merge ----
    for (int i = tid; i < KCB; i += 256) {
        int c = s_hist[i];
        if (c) atomicAdd(&g_cluster[i], (float)c);
    }
}

// ---------------------------------------------------------------------------
// dw: per-block smem accumulation, then one REDG merge (64 blocks x 512 thr)
// ---------------------------------------------------------------------------
__global__ __launch_bounds__(512)
void k_dw(const float* __restrict__ x, const float* __restrict__ idxf) {
    extern __shared__ float sdw[];          // [64][513]
    const int t = threadIdx.x;
    const int d = t & 63;
    const int rs = t >> 6;                  // 0..7
    const int base = blockIdx.x * 2048;
    for (int i = t; i < 64 * 513; i += 512) sdw[i] = 0.f;
    __syncthreads();
#pragma unroll 1
    for (int j0 = 0; j0 < 2048; j0 += 32) {
        float xv[4]; int cd[4];
#pragma unroll
        for (int u = 0; u < 4; u++) {
            int r = base + j0 + u * 8 + rs;
            cd[u] = (int)__ldg(&idxf[r]);
            xv[u] = __ldg(&x[(size_t)r * 64 + d]);
        }
#pragma unroll
        for (int u = 0; u < 4; u++)
            atomicAdd(&sdw[d * 513 + cd[u]], xv[u]);
    }
    __syncthreads();
    for (int i = t; i < 64 * 512; i += 512) {
        int dd = i >> 9, k = i & 511;
        float v = sdw[dd * 513 + k];
        if (v != 0.f) atomicAdd(&g_dw[i], v);
    }
}

// ---------------------------------------------------------------------------
// Finalize (grid 64 x 512): EMA, perplexity, loss, new embeddings
// ---------------------------------------------------------------------------
__global__ void k_final(const float* __restrict__ ehc,
                        const float* __restrict__ ehd,
                        const int* __restrict__ counter,
                        float* __restrict__ out) {
    __shared__ float red_n[512];
    __shared__ float red_p[512];

    const int k = threadIdx.x;
    const int d = blockIdx.x;
    const float one_minus_decay = 0.01f;

    float cn = g_cluster[k];
    float t = (float)(*counter + 1);
    float debias = 1.0f - powf(0.99f, t);
    float inv_debias = 1.0f / debias;

    float h    = ehc[k];
    float nhc  = h - (h - cn) * one_minus_decay;
    float avgc = nhc * inv_debias;

    red_n[k] = avgc;
    float p = cn * (1.0f / (float)NROWS);
    red_p[k] = (d == 0) ? p * logf(p + 1e-10f) : 0.f;
    __syncthreads();
#pragma unroll
    for (int s = 256; s > 0; s >>= 1) {
        if (k < s) { red_n[k] += red_n[k + s]; red_p[k] += red_p[k + s]; }
        __syncthreads();
    }
    float n_total = red_n[0];
    float smoothed = (avgc + 1e-5f) / (n_total + (float)KCB * 1e-5f) * n_total;

    float dw  = g_dw[d * KCB + k];
    float hd  = ehd[d * KCB + k];
    float nhd = hd - (hd - dw) * one_minus_decay;
    out[OFF_EMB + d * KCB + k] = (nhd * inv_debias) / smoothed;

    if (d == 0 && k == 0) {
        out[OFF_LOSS] = 0.25f * g_loss / (float)((size_t)NROWS * DDIM);
        out[OFF_PERP] = expf(-red_p[0]);
    }
}

// ---------------------------------------------------------------------------
extern "C" void kernel_launch(void* const* d_in, const int* in_sizes, int n_in,
                              void* d_out, int out_size) {
    const float* x       = (const float*)d_in[0];
    const float* emb     = (const float*)d_in[1];
    const float* ehc     = (const float*)d_in[2];
    const float* ehd     = (const float*)d_in[3];
    const int*   counter = (const int*)d_in[4];
    float* out = (float*)d_out;

    cudaFuncSetAttribute(k_main, cudaFuncAttributeMaxDynamicSharedMemorySize,
                         (int)SMEM_SZ);
    cudaFuncSetAttribute(k_dw, cudaFuncAttributeMaxDynamicSharedMemorySize,
                         64 * 513 * 4);

    k_prep<<<8, 512>>>(emb);
    k_zero_a<<<32, 512>>>();
    k_zero_b<<<32, 512>>>();
    k_main<<<GRID_MAIN, 256, SMEM_SZ>>>(x, emb, out + OFF_Q, out + OFF_IDX);
    k_dw<<<64, 512, 64 * 513 * 4>>>(x, out + OFF_IDX);
    k_final<<<64, 512>>>(ehc, ehd, counter, out);
}

// round 7
// speedup vs baseline: 2.5479x; 1.0081x over previous
#include <cuda_runtime.h>
#include <cuda_fp16.h>
#include <cstdint>
#include <math.h>

#define NROWS 131072
#define DDIM  64
#define KCB   512
#define TILE_M 256
#define NTILES (NROWS / TILE_M)     // 512
#define GRID_MAIN 148
#define THREADS 512

// Output layout (float32): q[NROWS*64], loss, perp, new_emb[64*512], idx[NROWS]
#define OFF_Q    0
#define OFF_LOSS (NROWS * DDIM)
#define OFF_PERP (OFF_LOSS + 1)
#define OFF_EMB  (OFF_PERP + 1)
#define OFF_IDX  (OFF_EMB + DDIM * KCB)

#define MARGIN 0.1875f
#define MASKH  0xFFFFFE00u
#define KEYBIAS 256.0f

// Device scratch
__device__ float g_dw[DDIM * KCB];
__device__ float g_cluster[KCB];
__device__ float g_loss;
__device__ float g_enorm[KCB];

__device__ __forceinline__ uint32_t pb(uint32_t d) {
    return ((d >> 1) & 3u) * 32u + (d >> 4) * 8u + ((d >> 3) & 1u) * 4u + (d & 1u) * 2u;
}

// smem layout (bytes)
#define SO_EH    0u          // 65536: e fp16 hi (packed, swizzled)
#define SO_EL    65536u      // 65536: e fp16 residual
#define SO_XH    131072u     // 32768: x fp16 (256 rows)
#define SO_EN2   163840u     // 2048:  ||e||^2 + KEYBIAS
#define SO_XN    165888u     // 1024:  per-row ||x||^2
#define SO_TOP   166912u     // 4096:  per-row top4 keys
#define SO_HIST  171008u     // 2048
#define SO_QUE   173056u     // 1024
#define SO_QN    174080u     // 4
#define SO_B64   174088u     // 8
#define SMEM_SZ  174112u

__device__ __forceinline__ void mma_f16(float* d, uint32_t a0, uint32_t a1,
                                        uint32_t a2, uint32_t a3,
                                        uint32_t b0, uint32_t b1) {
    asm volatile(
        "mma.sync.aligned.m16n8k16.row.col.f32.f16.f16.f32 "
        "{%0,%1,%2,%3}, {%4,%5,%6,%7}, {%8,%9}, {%0,%1,%2,%3};\n"
        : "+f"(d[0]), "+f"(d[1]), "+f"(d[2]), "+f"(d[3])
        : "r"(a0), "r"(a1), "r"(a2), "r"(a3), "r"(b0), "r"(b1));
}

__device__ __forceinline__ void ins4(uint32_t& m1, uint32_t& m2, uint32_t& m3,
                                     uint32_t& m4, uint32_t k) {
    uint32_t h1 = max(m1, k); m1 = min(m1, k);
    uint32_t h2 = max(m2, h1); m2 = min(m2, h1);
    uint32_t h3 = max(m3, h2); m3 = min(m3, h2);
    m4 = min(m4, h3);
}

// Exact fp32 squared distance: x row from GLOBAL, e = hi+lo fp16 from smem.
__device__ __forceinline__ float exact_dist_g(const float* __restrict__ xr,
                                              const char* sm, int code) {
    uint32_t ebase = (uint32_t)code * 128u;
    uint32_t xe = ((uint32_t)code & 7u) * 16u;
    float a0 = 0.f, a1 = 0.f, a2 = 0.f, a3 = 0.f;
#pragma unroll 8
    for (int p = 0; p < 32; p++) {
        uint32_t off = ebase + (((((uint32_t)p & 3u) * 32u) + (((uint32_t)p >> 3) * 8u)
                                + ((((uint32_t)p >> 2) & 1u) * 4u)) ^ xe);
        __half2 h2v = *(const __half2*)(sm + SO_EH + off);
        __half2 l2v = *(const __half2*)(sm + SO_EL + off);
        float2 xv = __ldg((const float2*)(xr + 2 * p));
        float e0 = __half2float(h2v.x) + __half2float(l2v.x);
        float e1 = __half2float(h2v.y) + __half2float(l2v.y);
        float t0 = xv.x - e0, t1 = xv.y - e1;
        if (p & 1) { a2 = fmaf(t0, t0, a2); a3 = fmaf(t1, t1, a3); }
        else       { a0 = fmaf(t0, t0, a0); a1 = fmaf(t1, t1, a1); }
    }
    return (a0 + a2) + (a1 + a3);
}

// ---------------------------------------------------------------------------
// Prep (grid 32): exact ||e_k||^2 (blocks 0-7) + zero all accumulators
// ---------------------------------------------------------------------------
__global__ void k_prep(const float* __restrict__ emb) {
    __shared__ float red[8][64];
    const int t = threadIdx.x, b = blockIdx.x;
    g_dw[b * 1024 + t] = 0.f;
    g_dw[b * 1024 + 512 + t] = 0.f;
    if (b < 8) {
        const int kk = t & 63, part = t >> 6;
        const int k = b * 64 + kk;
        float s = 0.f;
#pragma unroll
        for (int j = 0; j < 8; j++) {
            float e = emb[(part * 8 + j) * KCB + k];
            s = fmaf(e, e, s);
        }
        red[part][kk] = s;
        __syncthreads();
        if (t < 64) {
            float tot = red[0][t];
#pragma unroll
            for (int p = 1; p < 8; p++) tot += red[p][t];
            g_enorm[b * 64 + t] = tot;
        }
    }
    if (b == 31) {
        g_cluster[t] = 0.f;
        if (t == 0) g_loss = 0.f;
    }
}

// ---------------------------------------------------------------------------
// Main: 512 threads / 16 warps / 256-row tiles
// ---------------------------------------------------------------------------
__global__ __launch_bounds__(THREADS, 1)
void k_main(const float* __restrict__ x, const float* __restrict__ emb,
            float* __restrict__ out_q, float* __restrict__ out_idx) {
    extern __shared__ __align__(1024) char sm[];
    const int tid  = threadIdx.x;
    const int wid  = tid >> 5;
    const int lane = tid & 31;
    const int g    = lane >> 2;
    const int q    = lane & 3;

    float* s_en2  = (float*)(sm + SO_EN2);
    float* s_xn   = (float*)(sm + SO_XN);
    uint4* s_top  = (uint4*)(sm + SO_TOP);
    int*   s_hist = (int*)(sm + SO_HIST);
    int*   s_que  = (int*)(sm + SO_QUE);
    int*   s_qn   = (int*)(sm + SO_QN);
    unsigned long long* s_b64 = (unsigned long long*)(sm + SO_B64);

    // ---- Stage embeddings (fp16 hi + residual) ----
    for (int i = tid; i < DDIM * KCB; i += THREADS) {
        uint32_t d = (uint32_t)i >> 9, k = (uint32_t)i & 511u;
        float e = emb[i];
        __half h = __float2half_rn(e);
        __half l = __float2half_rn(e - __half2float(h));
        uint32_t off = k * 128u + (pb(d) ^ ((k & 7u) * 16u));
        *(__half*)(sm + SO_EH + off) = h;
        *(__half*)(sm + SO_EL + off) = l;
    }
    s_en2[tid] = g_enorm[tid] + KEYBIAS;
    s_hist[tid] = 0;
    __syncthreads();

    const int r0 = wid * 16 + g;
    const int r1 = r0 + 8;
    const uint32_t c0 = ((uint32_t)q * 32u) ^ ((uint32_t)g * 16u);
    const uint32_t c1 = ((uint32_t)q * 32u + 16u) ^ ((uint32_t)g * 16u);

    float loss_acc = 0.f;

    for (int tile = blockIdx.x; tile < NTILES; tile += gridDim.x) {
        const float* xt = x + (size_t)tile * TILE_M * DDIM;

        if (tid == 0) *s_qn = 0;
        // ---- Stage x tile (fp16) + per-row ||x||^2 ----
#pragma unroll
        for (int it = 0; it < 8; it++) {
            int i = it * THREADS + tid;
            float4 v = ((const float4*)xt)[i];
            uint32_t r = (uint32_t)i >> 4, c = ((uint32_t)i & 15u) * 4u;
            uint32_t xw = (r & 7u) * 16u;
            *(__half2*)(sm + SO_XH + r * 128u + (pb(c) ^ xw)) =
                __floats2half2_rn(v.x, v.y);
            *(__half2*)(sm + SO_XH + r * 128u + (pb(c + 2) ^ xw)) =
                __floats2half2_rn(v.z, v.w);
            float pn = fmaf(v.x, v.x, fmaf(v.y, v.y, fmaf(v.z, v.z, v.w * v.w)));
            pn += __shfl_xor_sync(0xffffffffu, pn, 1);
            pn += __shfl_xor_sync(0xffffffffu, pn, 2);
            pn += __shfl_xor_sync(0xffffffffu, pn, 4);
            pn += __shfl_xor_sync(0xffffffffu, pn, 8);
            if ((tid & 15) == 0) s_xn[r] = pn;
        }
        __syncthreads();

        // ---- A fragments ----
        uint4 A0a = *(const uint4*)(sm + SO_XH + (uint32_t)r0 * 128u + c0);
        uint4 A0b = *(const uint4*)(sm + SO_XH + (uint32_t)r0 * 128u + c1);
        uint4 A1a = *(const uint4*)(sm + SO_XH + (uint32_t)r1 * 128u + c0);
        uint4 A1b = *(const uint4*)(sm + SO_XH + (uint32_t)r1 * 128u + c1);

        // ---- Distance GEMM + top-4 key tracking ----
        uint32_t p11 = 0xFFFFFFFFu, p12 = 0xFFFFFFFFu, p13 = 0xFFFFFFFFu, p14 = 0xFFFFFFFFu;
        uint32_t p21 = 0xFFFFFFFFu, p22 = 0xFFFFFFFFu, p23 = 0xFFFFFFFFu, p24 = 0xFFFFFFFFu;

#pragma unroll 1
        for (int kb = 0; kb < 8; kb++) {
#pragma unroll 1
            for (int hh = 0; hh < 2; hh++) {
                float acc[4][4];
#pragma unroll
                for (int nt4 = 0; nt4 < 4; nt4++)
#pragma unroll
                    for (int j = 0; j < 4; j++) acc[nt4][j] = 0.f;

#pragma unroll
                for (int nt4 = 0; nt4 < 4; nt4++) {
                    int nt = hh * 4 + nt4;
                    uint32_t rowb = (uint32_t)(kb * 64 + nt * 8 + g) * 128u;
                    uint4 B0 = *(const uint4*)(sm + SO_EH + rowb + c0);
                    uint4 B1 = *(const uint4*)(sm + SO_EH + rowb + c1);
                    mma_f16(acc[nt4], A0a.x, A1a.x, A0a.y, A1a.y, B0.x, B0.y);
                    mma_f16(acc[nt4], A0a.z, A1a.z, A0a.w, A1a.w, B0.z, B0.w);
                    mma_f16(acc[nt4], A0b.x, A1b.x, A0b.y, A1b.y, B1.x, B1.y);
                    mma_f16(acc[nt4], A0b.z, A1b.z, A0b.w, A1b.w, B1.z, B1.w);
                }
#pragma unroll
                for (int nt4 = 0; nt4 < 4; nt4++) {
                    uint32_t n0 = (uint32_t)(kb * 64 + (hh * 4 + nt4) * 8 + q * 2);
                    float2 en = *(const float2*)&s_en2[n0];
                    uint32_t k0 = (__float_as_uint(fmaf(-2.f, acc[nt4][0], en.x)) & MASKH) | n0;
                    uint32_t k1 = (__float_as_uint(fmaf(-2.f, acc[nt4][1], en.y)) & MASKH) | (n0 + 1);
                    uint32_t k2 = (__float_as_uint(fmaf(-2.f, acc[nt4][2], en.x)) & MASKH) | n0;
                    uint32_t k3 = (__float_as_uint(fmaf(-2.f, acc[nt4][3], en.y)) & MASKH) | (n0 + 1);
                    ins4(p11, p12, p13, p14, k0);
                    ins4(p11, p12, p13, p14, k1);
                    ins4(p21, p22, p23, p24, k2);
                    ins4(p21, p22, p23, p24, k3);
                }
            }
        }

        // ---- Merge top-4 across quad lanes ----
#pragma unroll
        for (int o = 1; o <= 2; o <<= 1) {
            uint32_t q1 = __shfl_xor_sync(0xffffffffu, p11, o);
            uint32_t q2 = __shfl_xor_sync(0xffffffffu, p12, o);
            uint32_t q3 = __shfl_xor_sync(0xffffffffu, p13, o);
            uint32_t q4 = __shfl_xor_sync(0xffffffffu, p14, o);
            ins4(p11, p12, p13, p14, q1);
            ins4(p11, p12, p13, p14, q2);
            ins4(p11, p12, p13, p14, q3);
            ins4(p11, p12, p13, p14, q4);
            q1 = __shfl_xor_sync(0xffffffffu, p21, o);
            q2 = __shfl_xor_sync(0xffffffffu, p22, o);
            q3 = __shfl_xor_sync(0xffffffffu, p23, o);
            q4 = __shfl_xor_sync(0xffffffffu, p24, o);
            ins4(p21, p22, p23, p24, q1);
            ins4(p21, p22, p23, p24, q2);
            ins4(p21, p22, p23, p24, q3);
            ins4(p21, p22, p23, p24, q4);
        }
        if (q == 0) {
            s_top[r0] = make_uint4(p11, p12, p13, p14);
            s_top[r1] = make_uint4(p21, p22, p23, p24);
        }
        __syncthreads();

        // ---- Resolution + emission: 2 threads per row ----
        {
            const int rloc = tid >> 1;
            const int half = tid & 1;
            const int row  = tile * TILE_M + rloc;
            uint4 K = s_top[rloc];
            float d1 = __uint_as_float(K.x & MASKH);
            float d2 = __uint_as_float(K.y & MASKH);
            float d3 = __uint_as_float(K.z & MASKH);
            float d4 = __uint_as_float(K.w & MASKH);
            int i1 = (int)(K.x & 511u), i2 = (int)(K.y & 511u), i3 = (int)(K.z & 511u);
            int bidx = i1;
            bool emit = true;
            float lossv = d1 - KEYBIAS + s_xn[rloc];
            if (d2 - d1 >= MARGIN) {
                // accept i1
            } else if (d3 - d1 >= MARGIN) {
                const float* xr = x + (size_t)row * DDIM;
                float e1 = exact_dist_g(xr, sm, i1);
                float e2 = exact_dist_g(xr, sm, i2);
                if (e2 < e1 || (e2 == e1 && i2 < i1)) { bidx = i2; lossv = e2; }
                else lossv = e1;
            } else if (d4 - d1 >= MARGIN) {
                const float* xr = x + (size_t)row * DDIM;
                float e1 = exact_dist_g(xr, sm, i1);
                float e2 = exact_dist_g(xr, sm, i2);
                float e3 = exact_dist_g(xr, sm, i3);
                float be = e1;
                if (e2 < be || (e2 == be && i2 < bidx)) { be = e2; bidx = i2; }
                if (e3 < be || (e3 == be && i3 < bidx)) { be = e3; bidx = i3; }
                lossv = be;
            } else {
                emit = false;
                if (half == 0) {
                    int p = atomicAdd(s_qn, 1);
                    s_que[p] = rloc;
                }
            }
            if (emit) {
                if (half == 0) {
                    out_idx[row] = (float)bidx;
                    atomicAdd(&s_hist[bidx], 1);
                    loss_acc += lossv;
                }
                float* oq = out_q + (size_t)row * DDIM;
                uint32_t ebase = (uint32_t)bidx * 128u;
                uint32_t xe = ((uint32_t)bidx & 7u) * 16u;
#pragma unroll
                for (int d = half * 32; d < half * 32 + 32; d += 4) {
                    uint32_t oA = ebase + (pb((uint32_t)d) ^ xe);
                    uint32_t oB = ebase + (pb((uint32_t)d + 2) ^ xe);
                    __half2 h01 = *(__half2*)(sm + SO_EH + oA);
                    __half2 h23 = *(__half2*)(sm + SO_EH + oB);
                    __half2 l01 = *(__half2*)(sm + SO_EL + oA);
                    __half2 l23 = *(__half2*)(sm + SO_EL + oB);
                    float q0 = __half2float(h01.x) + __half2float(l01.x);
                    float q1 = __half2float(h01.y) + __half2float(l01.y);
                    float q2 = __half2float(h23.x) + __half2float(l23.x);
                    float q3 = __half2float(h23.y) + __half2float(l23.y);
                    *reinterpret_cast<float4*>(oq + d) = make_float4(q0, q1, q2, q3);
                }
            }
        }
        __syncthreads();

        // ---- Rare: block-cooperative exact rescan (1 code per thread) ----
        const int qn = *s_qn;
        for (int qi = 0; qi < qn; qi++) {
            if (tid == 0) *s_b64 = 0xFFFFFFFFFFFFFFFFull;
            __syncthreads();
            const int rloc = s_que[qi];
            const int row  = tile * TILE_M + rloc;
            const float* xr = x + (size_t)row * DDIM;
            float dv = exact_dist_g(xr, sm, tid);
            unsigned long long loc =
                (((unsigned long long)__float_as_uint(dv)) << 32) | (unsigned)tid;
#pragma unroll
            for (int o = 16; o > 0; o >>= 1) {
                unsigned long long ov = __shfl_xor_sync(0xffffffffu, loc, o);
                loc = min(loc, ov);
            }
            if (lane == 0) atomicMin(s_b64, loc);
            __syncthreads();
            const unsigned long long win = *s_b64;
            const int bidx = (int)(win & 511u);
            if (tid < 32) {
                int d = tid * 2;
                uint32_t ebase = (uint32_t)bidx * 128u;
                uint32_t xe = ((uint32_t)bidx & 7u) * 16u;
                uint32_t off = ebase + (pb((uint32_t)d) ^ xe);
                __half2 h2v = *(__half2*)(sm + SO_EH + off);
                __half2 l2v = *(__half2*)(sm + SO_EL + off);
                float q0 = __half2float(h2v.x) + __half2float(l2v.x);
                float q1 = __half2float(h2v.y) + __half2float(l2v.y);
                *(float2*)(out_q + (size_t)row * DDIM + d) = make_float2(q0, q1);
            }
            if (tid == 0) {
                out_idx[row] = (float)bidx;
                atomicAdd(&s_hist[bidx], 1);
                loss_acc += __uint_as_float((uint32_t)(win >> 32));
            }
            __syncthreads();
        }
        __syncthreads();
    }

    // ---- Loss: one atomic per warp ----
#pragma unroll
    for (int o = 16; o > 0; o >>= 1)
        loss_acc += __shfl_xor_sync(0xffffffffu, loss_acc, o);
    if (lane == 0) atomicAdd(&g_loss, loss_acc);

    // ---- Histogram merge ----
    {
        int c = s_hist[tid];
        if (c) atomicAdd(&g_cluster[tid], (float)c);
    }
}

// ---------------------------------------------------------------------------
// dw: per-block smem accumulation, then one REDG merge (64 blocks x 512 thr)
// ---------------------------------------------------------------------------
__global__ __launch_bounds__(512)
void k_dw(const float* __restrict__ x, const float* __restrict__ idxf) {
    extern __shared__ float sdw[];          // [64][513]
    const int t = threadIdx.x;
    const int d = t & 63;
    const int rs = t >> 6;                  // 0..7
    const int base = blockIdx.x * 2048;
    for (int i = t; i < 64 * 513; i += 512) sdw[i] = 0.f;
    __syncthreads();
#pragma unroll 1
    for (int j0 = 0; j0 < 2048; j0 += 32) {
        float xv[4]; int cd[4];
#pragma unroll
        for (int u = 0; u < 4; u++) {
            int r = base + j0 + u * 8 + rs;
            cd[u] = (int)__ldg(&idxf[r]);
            xv[u] = __ldg(&x[(size_t)r * 64 + d]);
        }
#pragma unroll
        for (int u = 0; u < 4; u++)
            atomicAdd(&sdw[d * 513 + cd[u]], xv[u]);
    }
    __syncthreads();
    for (int i = t; i < 64 * 512; i += 512) {
        int dd = i >> 9, k = i & 511;
        float v = sdw[dd * 513 + k];
        if (v != 0.f) atomicAdd(&g_dw[i], v);
    }
}

// ---------------------------------------------------------------------------
// Finalize (grid 64 x 512)
// ---------------------------------------------------------------------------
__global__ void k_final(const float* __restrict__ ehc,
                        const float* __restrict__ ehd,
                        const int* __restrict__ counter,
                        float* __restrict__ out) {
    __shared__ float red_n[512];
    __shared__ float red_p[512];

    const int k = threadIdx.x;
    const int d = blockIdx.x;
    const float one_minus_decay = 0.01f;

    float cn = g_cluster[k];
    float t = (float)(*counter + 1);
    float debias = 1.0f - powf(0.99f, t);
    float inv_debias = 1.0f / debias;

    float h    = ehc[k];
    float nhc  = h - (h - cn) * one_minus_decay;
    float avgc = nhc * inv_debias;

    red_n[k] = avgc;
    float p = cn * (1.0f / (float)NROWS);
    red_p[k] = (d == 0) ? p * logf(p + 1e-10f) : 0.f;
    __syncthreads();
#pragma unroll
    for (int s = 256; s > 0; s >>= 1) {
        if (k < s) { red_n[k] += red_n[k + s]; red_p[k] += red_p[k + s]; }
        __syncthreads();
    }
    float n_total = red_n[0];
    float smoothed = (avgc + 1e-5f) / (n_total + (float)KCB * 1e-5f) * n_total;

    float dw  = g_dw[d * KCB + k];
    float hd  = ehd[d * KCB + k];
    float nhd = hd - (hd - dw) * one_minus_decay;
    out[OFF_EMB + d * KCB + k] = (nhd * inv_debias) / smoothed;

    if (d == 0 && k == 0) {
        out[OFF_LOSS] = 0.25f * g_loss / (float)((size_t)NROWS * DDIM);
        out[OFF_PERP] = expf(-red_p[0]);
    }
}

// ---------------------------------------------------------------------------
extern "C" void kernel_launch(void* const* d_in, const int* in_sizes, int n_in,
                              void* d_out, int out_size) {
    const float* x       = (const float*)d_in[0];
    const float* emb     = (const float*)d_in[1];
    const float* ehc     = (const float*)d_in[2];
    const float* ehd     = (const float*)d_in[3];
    const int*   counter = (const int*)d_in[4];
    float* out = (float*)d_out;

    cudaFuncSetAttribute(k_main, cudaFuncAttributeMaxDynamicSharedMemorySize,
                         (int)SMEM_SZ);
    cudaFuncSetAttribute(k_dw, cudaFuncAttributeMaxDynamicSharedMemorySize,
                         64 * 513 * 4);

    k_prep<<<32, 512>>>(emb);
    k_main<<<GRID_MAIN, THREADS, SMEM_SZ>>>(x, emb, out + OFF_Q, out + OFF_IDX);
    k_dw<<<64, 512, 64 * 513 * 4>>>(x, out + OFF_IDX);
    k_final<<<64, 512>>>(ehc, ehd, counter, out);
}

// round 8
// speedup vs baseline: 2.7996x; 1.0988x over previous
#include <cuda_runtime.h>
#include <cuda_fp16.h>
#include <cstdint>
#include <math.h>

#define NROWS 131072
#define DDIM  64
#define KCB   512
#define TILE_M 256
#define NTILES (NROWS / TILE_M)     // 512
#define GRID_MAIN 148
#define THREADS 512

#define OFF_Q    0
#define OFF_LOSS (NROWS * DDIM)
#define OFF_PERP (OFF_LOSS + 1)
#define OFF_EMB  (OFF_PERP + 1)
#define OFF_IDX  (OFF_EMB + DDIM * KCB)

#define MARGIN 0.1875f
#define MASKH  0xFFFFFE00u
#define KEYBIAS 256.0f
#define SENT 0x7F7FFFFFu    // FLT_MAX bit pattern (valid for both int & float minmax)

__device__ float g_dw[DDIM * KCB];
__device__ float g_cluster[KCB];
__device__ float g_loss;
__device__ float g_enorm[KCB];

__device__ __forceinline__ uint32_t pb(uint32_t d) {
    return ((d >> 1) & 3u) * 32u + (d >> 4) * 8u + ((d >> 3) & 1u) * 4u + (d & 1u) * 2u;
}

// smem layout (bytes)
#define SO_EH    0u          // 65536
#define SO_EL    65536u      // 65536
#define SO_XH    131072u     // 32768
#define SO_EN2   163840u     // 2048
#define SO_XN    165888u     // 1024
#define SO_TOP   166912u     // 4096
#define SO_HIST  171008u     // 2048
#define SO_QUE   173056u     // 1024
#define SO_QN    174080u     // 4
#define SO_B64   174088u     // 8
#define SMEM_SZ  174112u

__device__ __forceinline__ void mma_f16(float* d, uint32_t a0, uint32_t a1,
                                        uint32_t a2, uint32_t a3,
                                        uint32_t b0, uint32_t b1) {
    asm volatile(
        "mma.sync.aligned.m16n8k16.row.col.f32.f16.f16.f32 "
        "{%0,%1,%2,%3}, {%4,%5,%6,%7}, {%8,%9}, {%0,%1,%2,%3};\n"
        : "+f"(d[0]), "+f"(d[1]), "+f"(d[2]), "+f"(d[3])
        : "r"(a0), "r"(a1), "r"(a2), "r"(a3), "r"(b0), "r"(b1));
}

// integer top-4 insert (ALU pipe): 7 IMNMX
__device__ __forceinline__ void ins4(uint32_t& m1, uint32_t& m2, uint32_t& m3,
                                     uint32_t& m4, uint32_t k) {
    uint32_t h1 = max(m1, k); m1 = min(m1, k);
    uint32_t h2 = max(m2, h1); m2 = min(m2, h1);
    uint32_t h3 = max(m3, h2); m3 = min(m3, h2);
    m4 = min(m4, h3);
}
// float top-4 insert (FMA pipe): 7 FMNMX (all values positive finite)
__device__ __forceinline__ void ins4f(float& m1, float& m2, float& m3,
                                      float& m4, float k) {
    float h1 = fmaxf(m1, k); m1 = fminf(m1, k);
    float h2 = fmaxf(m2, h1); m2 = fminf(m2, h1);
    float h3 = fmaxf(m3, h2); m3 = fminf(m3, h2);
    m4 = fminf(m4, h3);
}
// key = dist bits with low 9 bits replaced by index (1 BFI)
__device__ __forceinline__ uint32_t mkkey(float dist, uint32_t n) {
    uint32_t r;
    asm("bfi.b32 %0, %1, %2, 0, 9;" : "=r"(r) : "r"(n), "r"(__float_as_uint(dist)));
    return r;
}

__device__ __forceinline__ float exact_dist_g(const float* __restrict__ xr,
                                              const char* sm, int code) {
    uint32_t ebase = (uint32_t)code * 128u;
    uint32_t xe = ((uint32_t)code & 7u) * 16u;
    float a0 = 0.f, a1 = 0.f, a2 = 0.f, a3 = 0.f;
#pragma unroll 8
    for (int p = 0; p < 32; p++) {
        uint32_t off = ebase + (((((uint32_t)p & 3u) * 32u) + (((uint32_t)p >> 3) * 8u)
                                + ((((uint32_t)p >> 2) & 1u) * 4u)) ^ xe);
        __half2 h2v = *(const __half2*)(sm + SO_EH + off);
        __half2 l2v = *(const __half2*)(sm + SO_EL + off);
        float2 xv = __ldg((const float2*)(xr + 2 * p));
        float e0 = __half2float(h2v.x) + __half2float(l2v.x);
        float e1 = __half2float(h2v.y) + __half2float(l2v.y);
        float t0 = xv.x - e0, t1 = xv.y - e1;
        if (p & 1) { a2 = fmaf(t0, t0, a2); a3 = fmaf(t1, t1, a3); }
        else       { a0 = fmaf(t0, t0, a0); a1 = fmaf(t1, t1, a1); }
    }
    return (a0 + a2) + (a1 + a3);
}

// ---------------------------------------------------------------------------
__global__ void k_prep(const float* __restrict__ emb) {
    __shared__ float red[8][64];
    const int t = threadIdx.x, b = blockIdx.x;
    const int kk = t & 63, part = t >> 6;
    const int k = b * 64 + kk;
    float s = 0.f;
#pragma unroll
    for (int j = 0; j < 8; j++) {
        float e = emb[(part * 8 + j) * KCB + k];
        s = fmaf(e, e, s);
    }
    red[part][kk] = s;
    __syncthreads();
    if (t < 64) {
        float tot = red[0][t];
#pragma unroll
        for (int p = 1; p < 8; p++) tot += red[p][t];
        g_enorm[b * 64 + t] = tot;
    }
    if (b == 0) {
        g_cluster[t] = 0.f;
        if (t == 0) g_loss = 0.f;
    }
}
__global__ void k_zero_a() { g_dw[blockIdx.x * 512 + threadIdx.x] = 0.f; }
__global__ void k_zero_b() { g_dw[16384 + blockIdx.x * 512 + threadIdx.x] = 0.f; }

// ---------------------------------------------------------------------------
__global__ __launch_bounds__(THREADS, 1)
void k_main(const float* __restrict__ x, const float* __restrict__ emb,
            float* __restrict__ out_q, float* __restrict__ out_idx) {
    extern __shared__ __align__(1024) char sm[];
    const int tid  = threadIdx.x;
    const int wid  = tid >> 5;
    const int lane = tid & 31;
    const int g    = lane >> 2;
    const int q    = lane & 3;

    float* s_en2  = (float*)(sm + SO_EN2);
    float* s_xn   = (float*)(sm + SO_XN);
    uint4* s_top  = (uint4*)(sm + SO_TOP);
    int*   s_hist = (int*)(sm + SO_HIST);
    int*   s_que  = (int*)(sm + SO_QUE);
    int*   s_qn   = (int*)(sm + SO_QN);
    unsigned long long* s_b64 = (unsigned long long*)(sm + SO_B64);

    for (int i = tid; i < DDIM * KCB; i += THREADS) {
        uint32_t d = (uint32_t)i >> 9, k = (uint32_t)i & 511u;
        float e = emb[i];
        __half h = __float2half_rn(e);
        __half l = __float2half_rn(e - __half2float(h));
        uint32_t off = k * 128u + (pb(d) ^ ((k & 7u) * 16u));
        *(__half*)(sm + SO_EH + off) = h;
        *(__half*)(sm + SO_EL + off) = l;
    }
    s_en2[tid] = g_enorm[tid] + KEYBIAS;
    s_hist[tid] = 0;
    __syncthreads();

    const int r0 = wid * 16 + g;
    const int r1 = r0 + 8;
    const uint32_t c0 = ((uint32_t)q * 32u) ^ ((uint32_t)g * 16u);
    const uint32_t c1 = ((uint32_t)q * 32u + 16u) ^ ((uint32_t)g * 16u);

    float loss_acc = 0.f;

    for (int tile = blockIdx.x; tile < NTILES; tile += gridDim.x) {
        const float* xt = x + (size_t)tile * TILE_M * DDIM;

        if (tid == 0) *s_qn = 0;
#pragma unroll
        for (int it = 0; it < 8; it++) {
            int i = it * THREADS + tid;
            float4 v = ((const float4*)xt)[i];
            uint32_t r = (uint32_t)i >> 4, c = ((uint32_t)i & 15u) * 4u;
            uint32_t xw = (r & 7u) * 16u;
            *(__half2*)(sm + SO_XH + r * 128u + (pb(c) ^ xw)) =
                __floats2half2_rn(v.x, v.y);
            *(__half2*)(sm + SO_XH + r * 128u + (pb(c + 2) ^ xw)) =
                __floats2half2_rn(v.z, v.w);
            float pn = fmaf(v.x, v.x, fmaf(v.y, v.y, fmaf(v.z, v.z, v.w * v.w)));
            pn += __shfl_xor_sync(0xffffffffu, pn, 1);
            pn += __shfl_xor_sync(0xffffffffu, pn, 2);
            pn += __shfl_xor_sync(0xffffffffu, pn, 4);
            pn += __shfl_xor_sync(0xffffffffu, pn, 8);
            if ((tid & 15) == 0) s_xn[r] = pn;
        }
        __syncthreads();

        uint4 A0a = *(const uint4*)(sm + SO_XH + (uint32_t)r0 * 128u + c0);
        uint4 A0b = *(const uint4*)(sm + SO_XH + (uint32_t)r0 * 128u + c1);
        uint4 A1a = *(const uint4*)(sm + SO_XH + (uint32_t)r1 * 128u + c0);
        uint4 A1b = *(const uint4*)(sm + SO_XH + (uint32_t)r1 * 128u + c1);

        // row0 top-4: uint keys on ALU pipe; row1 top-4: float keys on FMA pipe
        uint32_t p11 = SENT, p12 = SENT, p13 = SENT, p14 = SENT;
        float    f21 = __uint_as_float(SENT), f22 = f21, f23 = f21, f24 = f21;

#pragma unroll 1
        for (int kb = 0; kb < 8; kb++) {
            float acc[8][4];
#pragma unroll
            for (int nt = 0; nt < 8; nt++)
#pragma unroll
                for (int j = 0; j < 4; j++) acc[nt][j] = 0.f;

#pragma unroll
            for (int nt = 0; nt < 8; nt++) {
                uint32_t rowb = (uint32_t)(kb * 64 + nt * 8 + g) * 128u;
                uint4 B0 = *(const uint4*)(sm + SO_EH + rowb + c0);
                uint4 B1 = *(const uint4*)(sm + SO_EH + rowb + c1);
                mma_f16(acc[nt], A0a.x, A1a.x, A0a.y, A1a.y, B0.x, B0.y);
                mma_f16(acc[nt], A0a.z, A1a.z, A0a.w, A1a.w, B0.z, B0.w);
                mma_f16(acc[nt], A0b.x, A1b.x, A0b.y, A1b.y, B1.x, B1.y);
                mma_f16(acc[nt], A0b.z, A1b.z, A0b.w, A1b.w, B1.z, B1.w);
            }
#pragma unroll
            for (int nt = 0; nt < 8; nt++) {
                uint32_t n0 = (uint32_t)(kb * 64 + nt * 8 + q * 2);
                float2 en = *(const float2*)&s_en2[n0];
                // row0 -> integer pipe
                uint32_t k0 = mkkey(fmaf(-2.f, acc[nt][0], en.x), n0);
                uint32_t k1 = mkkey(fmaf(-2.f, acc[nt][1], en.y), n0 + 1);
                ins4(p11, p12, p13, p14, k0);
                ins4(p11, p12, p13, p14, k1);
                // row1 -> float pipe
                float k2 = __uint_as_float(mkkey(fmaf(-2.f, acc[nt][2], en.x), n0));
                float k3 = __uint_as_float(mkkey(fmaf(-2.f, acc[nt][3], en.y), n0 + 1));
                ins4f(f21, f22, f23, f24, k2);
                ins4f(f21, f22, f23, f24, k3);
            }
        }

        // merge across quad lanes
#pragma unroll
        for (int o = 1; o <= 2; o <<= 1) {
            uint32_t q1 = __shfl_xor_sync(0xffffffffu, p11, o);
            uint32_t q2 = __shfl_xor_sync(0xffffffffu, p12, o);
            uint32_t q3 = __shfl_xor_sync(0xffffffffu, p13, o);
            uint32_t q4 = __shfl_xor_sync(0xffffffffu, p14, o);
            ins4(p11, p12, p13, p14, q1);
            ins4(p11, p12, p13, p14, q2);
            ins4(p11, p12, p13, p14, q3);
            ins4(p11, p12, p13, p14, q4);
            float s1 = __shfl_xor_sync(0xffffffffu, f21, o);
            float s2 = __shfl_xor_sync(0xffffffffu, f22, o);
            float s3 = __shfl_xor_sync(0xffffffffu, f23, o);
            float s4 = __shfl_xor_sync(0xffffffffu, f24, o);
            ins4f(f21, f22, f23, f24, s1);
            ins4f(f21, f22, f23, f24, s2);
            ins4f(f21, f22, f23, f24, s3);
            ins4f(f21, f22, f23, f24, s4);
        }
        if (q == 0) {
            s_top[r0] = make_uint4(p11, p12, p13, p14);
            s_top[r1] = make_uint4(__float_as_uint(f21), __float_as_uint(f22),
                                   __float_as_uint(f23), __float_as_uint(f24));
        }
        __syncthreads();

        // ---- Resolution + emission: 2 threads per row ----
        {
            const int rloc = tid >> 1;
            const int half = tid & 1;
            const int row  = tile * TILE_M + rloc;
            uint4 K = s_top[rloc];
            float d1 = __uint_as_float(K.x & MASKH);
            float d2 = __uint_as_float(K.y & MASKH);
            float d3 = __uint_as_float(K.z & MASKH);
            float d4 = __uint_as_float(K.w & MASKH);
            int i1 = (int)(K.x & 511u), i2 = (int)(K.y & 511u), i3 = (int)(K.z & 511u);
            int bidx = i1;
            bool emit = true;
            float lossv = d1 - KEYBIAS + s_xn[rloc];
            if (d2 - d1 >= MARGIN) {
            } else if (d3 - d1 >= MARGIN) {
                const float* xr = x + (size_t)row * DDIM;
                float e1 = exact_dist_g(xr, sm, i1);
                float e2 = exact_dist_g(xr, sm, i2);
                if (e2 < e1 || (e2 == e1 && i2 < i1)) { bidx = i2; lossv = e2; }
                else lossv = e1;
            } else if (d4 - d1 >= MARGIN) {
                const float* xr = x + (size_t)row * DDIM;
                float e1 = exact_dist_g(xr, sm, i1);
                float e2 = exact_dist_g(xr, sm, i2);
                float e3 = exact_dist_g(xr, sm, i3);
                float be = e1;
                if (e2 < be || (e2 == be && i2 < bidx)) { be = e2; bidx = i2; }
                if (e3 < be || (e3 == be && i3 < bidx)) { be = e3; bidx = i3; }
                lossv = be;
            } else {
                emit = false;
                if (half == 0) {
                    int p = atomicAdd(s_qn, 1);
                    s_que[p] = rloc;
                }
            }
            if (emit) {
                if (half == 0) {
                    out_idx[row] = (float)bidx;
                    atomicAdd(&s_hist[bidx], 1);
                    loss_acc += lossv;
                }
                float* oq = out_q + (size_t)row * DDIM;
                uint32_t ebase = (uint32_t)bidx * 128u;
                uint32_t xe = ((uint32_t)bidx & 7u) * 16u;
#pragma unroll
                for (int d = half * 32; d < half * 32 + 32; d += 4) {
                    uint32_t oA = ebase + (pb((uint32_t)d) ^ xe);
                    uint32_t oB = ebase + (pb((uint32_t)d + 2) ^ xe);
                    __half2 h01 = *(__half2*)(sm + SO_EH + oA);
                    __half2 h23 = *(__half2*)(sm + SO_EH + oB);
                    __half2 l01 = *(__half2*)(sm + SO_EL + oA);
                    __half2 l23 = *(__half2*)(sm + SO_EL + oB);
                    float q0 = __half2float(h01.x) + __half2float(l01.x);
                    float q1 = __half2float(h01.y) + __half2float(l01.y);
                    float q2 = __half2float(h23.x) + __half2float(l23.x);
                    float q3 = __half2float(h23.y) + __half2float(l23.y);
                    *reinterpret_cast<float4*>(oq + d) = make_float4(q0, q1, q2, q3);
                }
            }
        }
        __syncthreads();

        // ---- Rare: block-cooperative exact rescan ----
        const int qn = *s_qn;
        for (int qi = 0; qi < qn; qi++) {
            if (tid == 0) *s_b64 = 0xFFFFFFFFFFFFFFFFull;
            __syncthreads();
            const int rloc = s_que[qi];
            const int row  = tile * TILE_M + rloc;
            const float* xr = x + (size_t)row * DDIM;
            float dv = exact_dist_g(xr, sm, tid);
            unsigned long long loc =
                (((unsigned long long)__float_as_uint(dv)) << 32) | (unsigned)tid;
#pragma unroll
            for (int o = 16; o > 0; o >>= 1) {
                unsigned long long ov = __shfl_xor_sync(0xffffffffu, loc, o);
                loc = min(loc, ov);
            }
            if (lane == 0) atomicMin(s_b64, loc);
            __syncthreads();
            const unsigned long long win = *s_b64;
            const int bidx = (int)(win & 511u);
            if (tid < 32) {
                int d = tid * 2;
                uint32_t ebase = (uint32_t)bidx * 128u;
                uint32_t xe = ((uint32_t)bidx & 7u) * 16u;
                uint32_t off = ebase + (pb((uint32_t)d) ^ xe);
                __half2 h2v = *(__half2*)(sm + SO_EH + off);
                __half2 l2v = *(__half2*)(sm + SO_EL + off);
                float q0 = __half2float(h2v.x) + __half2float(l2v.x);
                float q1 = __half2float(h2v.y) + __half2float(l2v.y);
                *(float2*)(out_q + (size_t)row * DDIM + d) = make_float2(q0, q1);
            }
            if (tid == 0) {
                out_idx[row] = (float)bidx;
                atomicAdd(&s_hist[bidx], 1);
                loss_acc += __uint_as_float((uint32_t)(win >> 32));
            }
            __syncthreads();
        }
        __syncthreads();
    }

#pragma unroll
    for (int o = 16; o > 0; o >>= 1)
        loss_acc += __shfl_xor_sync(0xffffffffu, loss_acc, o);
    if (lane == 0) atomicAdd(&g_loss, loss_acc);

    {
        int c = s_hist[tid];
        if (c) atomicAdd(&g_cluster[tid], (float)c);
    }
}

// ---------------------------------------------------------------------------
// dw: 128 blocks x 512 thr; consecutive-row run combining + smem accumulation
// ---------------------------------------------------------------------------
__global__ __launch_bounds__(512)
void k_dw(const float* __restrict__ x, const float* __restrict__ idxf) {
    extern __shared__ float sdw[];          // [64][513]
    const int t = threadIdx.x;
    const int d = t & 63;
    const int rs = t >> 6;                  // 0..7
    const int base = blockIdx.x * 1024;
    for (int i = t; i < 64 * 513; i += 512) sdw[i] = 0.f;
    __syncthreads();
#pragma unroll 1
    for (int j0 = 0; j0 < 1024; j0 += 32) {
        float xv[4]; int cd[4];
#pragma unroll
        for (int u = 0; u < 4; u++) {
            int r = base + j0 + rs * 4 + u;       // 4 consecutive rows
            cd[u] = (int)__ldg(&idxf[r]);
            xv[u] = __ldg(&x[(size_t)r * 64 + d]);
        }
        // run-combine equal consecutive codes (image data => frequent)
        float s = xv[0]; int c = cd[0];
#pragma unroll
        for (int u = 1; u < 4; u++) {
            if (cd[u] == c) s += xv[u];
            else { atomicAdd(&sdw[d * 513 + c], s); c = cd[u]; s = xv[u]; }
        }
        atomicAdd(&sdw[d * 513 + c], s);
    }
    __syncthreads();
    for (int i = t; i < 64 * 512; i += 512) {
        int dd = i >> 9, k = i & 511;
        float v = sdw[dd * 513 + k];
        if (v != 0.f) atomicAdd(&g_dw[i], v);
    }
}

// ---------------------------------------------------------------------------
__global__ void k_final(const float* __restrict__ ehc,
                        const float* __restrict__ ehd,
                        const int* __restrict__ counter,
                        float* __restrict__ out) {
    __shared__ float red_n[512];
    __shared__ float red_p[512];

    const int k = threadIdx.x;
    const int d = blockIdx.x;
    const float one_minus_decay = 0.01f;

    float cn = g_cluster[k];
    float t = (float)(*counter + 1);
    float debias = 1.0f - powf(0.99f, t);
    float inv_debias = 1.0f / debias;

    float h    = ehc[k];
    float nhc  = h - (h - cn) * one_minus_decay;
    float avgc = nhc * inv_debias;

    red_n[k] = avgc;
    float p = cn * (1.0f / (float)NROWS);
    red_p[k] = (d == 0) ? p * logf(p + 1e-10f) : 0.f;
    __syncthreads();
#pragma unroll
    for (int s = 256; s > 0; s >>= 1) {
        if (k < s) { red_n[k] += red_n[k + s]; red_p[k] += red_p[k + s]; }
        __syncthreads();
    }
    float n_total = red_n[0];
    float smoothed = (avgc + 1e-5f) / (n_total + (float)KCB * 1e-5f) * n_total;

    float dw  = g_dw[d * KCB + k];
    float hd  = ehd[d * KCB + k];
    float nhd = hd - (hd - dw) * one_minus_decay;
    out[OFF_EMB + d * KCB + k] = (nhd * inv_debias) / smoothed;

    if (d == 0 && k == 0) {
        out[OFF_LOSS] = 0.25f * g_loss / (float)((size_t)NROWS * DDIM);
        out[OFF_PERP] = expf(-red_p[0]);
    }
}

// ---------------------------------------------------------------------------
extern "C" void kernel_launch(void* const* d_in, const int* in_sizes, int n_in,
                              void* d_out, int out_size) {
    const float* x       = (const float*)d_in[0];
    const float* emb     = (const float*)d_in[1];
    const float* ehc     = (const float*)d_in[2];
    const float* ehd     = (const float*)d_in[3];
    const int*   counter = (const int*)d_in[4];
    float* out = (float*)d_out;

    cudaFuncSetAttribute(k_main, cudaFuncAttributeMaxDynamicSharedMemorySize,
                         (int)SMEM_SZ);
    cudaFuncSetAttribute(k_dw, cudaFuncAttributeMaxDynamicSharedMemorySize,
                         64 * 513 * 4);

    k_prep<<<8, 512>>>(emb);
    k_zero_a<<<32, 512>>>();
    k_zero_b<<<32, 512>>>();
    k_main<<<GRID_MAIN, THREADS, SMEM_SZ>>>(x, emb, out + OFF_Q, out + OFF_IDX);
    k_dw<<<128, 512, 64 * 513 * 4>>>(x, out + OFF_IDX);
    k_final<<<64, 512>>>(ehc, ehd, counter, out);
}

// round 9
// speedup vs baseline: 2.9823x; 1.0653x over previous
#include <cuda_runtime.h>
#include <cuda_fp16.h>
#include <cstdint>
#include <math.h>

#define NROWS 131072
#define DDIM  64
#define KCB   512
#define TILE_M 256
#define NTILES (NROWS / TILE_M)     // 512
#define GRID_MAIN 148
#define THREADS 512

#define OFF_Q    0
#define OFF_LOSS (NROWS * DDIM)
#define OFF_PERP (OFF_LOSS + 1)
#define OFF_EMB  (OFF_PERP + 1)
#define OFF_IDX  (OFF_EMB + DDIM * KCB)

#define MARGIN 0.1875f
#define MASKH  0xFFFFFE00u
#define KEYBIAS 256.0f
#define SENT 0x7F7FFFFFu

__device__ float g_dw[DDIM * KCB];
__device__ float g_cluster[KCB];
__device__ float g_loss;
__device__ float g_enorm[KCB];

__device__ __forceinline__ uint32_t pb(uint32_t d) {
    return ((d >> 1) & 3u) * 32u + (d >> 4) * 8u + ((d >> 3) & 1u) * 4u + (d & 1u) * 2u;
}

// smem layout (bytes)
#define SO_EH    0u          // 65536
#define SO_EL    65536u      // 65536
#define SO_XH    131072u     // 32768
#define SO_EN2   163840u     // 2048
#define SO_XN    165888u     // 1024
#define SO_TOP   166912u     // 4096
#define SO_HIST  171008u     // 2048
#define SO_QUE   173056u     // 1024 duel queue
#define SO_QUE2  174080u     // 1024 rescan queue
#define SO_QN    175104u     // 4
#define SO_QN2   175108u     // 4
#define SO_B64   175112u     // 8
#define SMEM_SZ  175136u

__device__ __forceinline__ void mma_f16(float* d, uint32_t a0, uint32_t a1,
                                        uint32_t a2, uint32_t a3,
                                        uint32_t b0, uint32_t b1) {
    asm volatile(
        "mma.sync.aligned.m16n8k16.row.col.f32.f16.f16.f32 "
        "{%0,%1,%2,%3}, {%4,%5,%6,%7}, {%8,%9}, {%0,%1,%2,%3};\n"
        : "+f"(d[0]), "+f"(d[1]), "+f"(d[2]), "+f"(d[3])
        : "r"(a0), "r"(a1), "r"(a2), "r"(a3), "r"(b0), "r"(b1));
}

__device__ __forceinline__ void ins4(uint32_t& m1, uint32_t& m2, uint32_t& m3,
                                     uint32_t& m4, uint32_t k) {
    uint32_t h1 = max(m1, k); m1 = min(m1, k);
    uint32_t h2 = max(m2, h1); m2 = min(m2, h1);
    uint32_t h3 = max(m3, h2); m3 = min(m3, h2);
    m4 = min(m4, h3);
}
__device__ __forceinline__ uint32_t mkkey(float dist, uint32_t n) {
    uint32_t r;
    asm("bfi.b32 %0, %1, %2, 0, 9;" : "=r"(r) : "r"(n), "r"(__float_as_uint(dist)));
    return r;
}

// ---------------------------------------------------------------------------
__global__ void k_prep(const float* __restrict__ emb) {
    __shared__ float red[8][64];
    const int t = threadIdx.x, b = blockIdx.x;
    const int kk = t & 63, part = t >> 6;
    const int k = b * 64 + kk;
    float s = 0.f;
#pragma unroll
    for (int j = 0; j < 8; j++) {
        float e = emb[(part * 8 + j) * KCB + k];
        s = fmaf(e, e, s);
    }
    red[part][kk] = s;
    __syncthreads();
    if (t < 64) {
        float tot = red[0][t];
#pragma unroll
        for (int p = 1; p < 8; p++) tot += red[p][t];
        g_enorm[b * 64 + t] = tot;
    }
    if (b == 0) {
        g_cluster[t] = 0.f;
        if (t == 0) g_loss = 0.f;
    }
}
__global__ void k_zero_a() { g_dw[blockIdx.x * 512 + threadIdx.x] = 0.f; }
__global__ void k_zero_b() { g_dw[16384 + blockIdx.x * 512 + threadIdx.x] = 0.f; }

// ---------------------------------------------------------------------------
__global__ __launch_bounds__(THREADS, 1)
void k_main(const float* __restrict__ x, const float* __restrict__ emb,
            float* __restrict__ out_q, float* __restrict__ out_idx) {
    extern __shared__ __align__(1024) char sm[];
    const int tid  = threadIdx.x;
    const int wid  = tid >> 5;
    const int lane = tid & 31;
    const int g    = lane >> 2;
    const int q    = lane & 3;

    float* s_en2  = (float*)(sm + SO_EN2);
    float* s_xn   = (float*)(sm + SO_XN);
    uint4* s_top  = (uint4*)(sm + SO_TOP);
    int*   s_hist = (int*)(sm + SO_HIST);
    int*   s_que  = (int*)(sm + SO_QUE);
    int*   s_que2 = (int*)(sm + SO_QUE2);
    int*   s_qn   = (int*)(sm + SO_QN);
    int*   s_qn2  = (int*)(sm + SO_QN2);
    unsigned long long* s_b64 = (unsigned long long*)(sm + SO_B64);

    for (int i = tid; i < DDIM * KCB; i += THREADS) {
        uint32_t d = (uint32_t)i >> 9, k = (uint32_t)i & 511u;
        float e = emb[i];
        __half h = __float2half_rn(e);
        __half l = __float2half_rn(e - __half2float(h));
        uint32_t off = k * 128u + (pb(d) ^ ((k & 7u) * 16u));
        *(__half*)(sm + SO_EH + off) = h;
        *(__half*)(sm + SO_EL + off) = l;
    }
    s_en2[tid] = g_enorm[tid] + KEYBIAS;
    s_hist[tid] = 0;
    __syncthreads();

    const int r0 = wid * 16 + g;
    const int r1 = r0 + 8;
    const uint32_t c0 = ((uint32_t)q * 32u) ^ ((uint32_t)g * 16u);
    const uint32_t c1 = ((uint32_t)q * 32u + 16u) ^ ((uint32_t)g * 16u);

    float loss_acc = 0.f;

    for (int tile = blockIdx.x; tile < NTILES; tile += gridDim.x) {
        const float* xt = x + (size_t)tile * TILE_M * DDIM;

        if (tid == 0) { *s_qn = 0; *s_qn2 = 0; }
#pragma unroll
        for (int it = 0; it < 8; it++) {
            int i = it * THREADS + tid;
            float4 v = ((const float4*)xt)[i];
            uint32_t r = (uint32_t)i >> 4, c = ((uint32_t)i & 15u) * 4u;
            uint32_t xw = (r & 7u) * 16u;
            *(__half2*)(sm + SO_XH + r * 128u + (pb(c) ^ xw)) =
                __floats2half2_rn(v.x, v.y);
            *(__half2*)(sm + SO_XH + r * 128u + (pb(c + 2) ^ xw)) =
                __floats2half2_rn(v.z, v.w);
            float pn = fmaf(v.x, v.x, fmaf(v.y, v.y, fmaf(v.z, v.z, v.w * v.w)));
            pn += __shfl_xor_sync(0xffffffffu, pn, 1);
            pn += __shfl_xor_sync(0xffffffffu, pn, 2);
            pn += __shfl_xor_sync(0xffffffffu, pn, 4);
            pn += __shfl_xor_sync(0xffffffffu, pn, 8);
            if ((tid & 15) == 0) s_xn[r] = pn;
        }
        __syncthreads();

        uint4 A0a = *(const uint4*)(sm + SO_XH + (uint32_t)r0 * 128u + c0);
        uint4 A0b = *(const uint4*)(sm + SO_XH + (uint32_t)r0 * 128u + c1);
        uint4 A1a = *(const uint4*)(sm + SO_XH + (uint32_t)r1 * 128u + c0);
        uint4 A1b = *(const uint4*)(sm + SO_XH + (uint32_t)r1 * 128u + c1);

        uint32_t p11 = SENT, p12 = SENT, p13 = SENT, p14 = SENT;
        uint32_t p21 = SENT, p22 = SENT, p23 = SENT, p24 = SENT;

#pragma unroll 1
        for (int kb = 0; kb < 8; kb++) {
            float acc[8][4];
#pragma unroll
            for (int nt = 0; nt < 8; nt++)
#pragma unroll
                for (int j = 0; j < 4; j++) acc[nt][j] = 0.f;

#pragma unroll
            for (int nt = 0; nt < 8; nt++) {
                uint32_t rowb = (uint32_t)(kb * 64 + nt * 8 + g) * 128u;
                uint4 B0 = *(const uint4*)(sm + SO_EH + rowb + c0);
                uint4 B1 = *(const uint4*)(sm + SO_EH + rowb + c1);
                mma_f16(acc[nt], A0a.x, A1a.x, A0a.y, A1a.y, B0.x, B0.y);
                mma_f16(acc[nt], A0a.z, A1a.z, A0a.w, A1a.w, B0.z, B0.w);
                mma_f16(acc[nt], A0b.x, A1b.x, A0b.y, A1b.y, B1.x, B1.y);
                mma_f16(acc[nt], A0b.z, A1b.z, A0b.w, A1b.w, B1.z, B1.w);
            }
#pragma unroll
            for (int nt = 0; nt < 8; nt++) {
                uint32_t n0 = (uint32_t)(kb * 64 + nt * 8 + q * 2);
                float2 en = *(const float2*)&s_en2[n0];
                uint32_t k0 = mkkey(fmaf(-2.f, acc[nt][0], en.x), n0);
                uint32_t k1 = mkkey(fmaf(-2.f, acc[nt][1], en.y), n0 + 1);
                uint32_t k2 = mkkey(fmaf(-2.f, acc[nt][2], en.x), n0);
                uint32_t k3 = mkkey(fmaf(-2.f, acc[nt][3], en.y), n0 + 1);
                ins4(p11, p12, p13, p14, k0);
                ins4(p11, p12, p13, p14, k1);
                ins4(p21, p22, p23, p24, k2);
                ins4(p21, p22, p23, p24, k3);
            }
        }

#pragma unroll
        for (int o = 1; o <= 2; o <<= 1) {
            uint32_t q1 = __shfl_xor_sync(0xffffffffu, p11, o);
            uint32_t q2 = __shfl_xor_sync(0xffffffffu, p12, o);
            uint32_t q3 = __shfl_xor_sync(0xffffffffu, p13, o);
            uint32_t q4 = __shfl_xor_sync(0xffffffffu, p14, o);
            ins4(p11, p12, p13, p14, q1);
            ins4(p11, p12, p13, p14, q2);
            ins4(p11, p12, p13, p14, q3);
            ins4(p11, p12, p13, p14, q4);
            q1 = __shfl_xor_sync(0xffffffffu, p21, o);
            q2 = __shfl_xor_sync(0xffffffffu, p22, o);
            q3 = __shfl_xor_sync(0xffffffffu, p23, o);
            q4 = __shfl_xor_sync(0xffffffffu, p24, o);
            ins4(p21, p22, p23, p24, q1);
            ins4(p21, p22, p23, p24, q2);
            ins4(p21, p22, p23, p24, q3);
            ins4(p21, p22, p23, p24, q4);
        }
        if (q == 0) {
            s_top[r0] = make_uint4(p11, p12, p13, p14);
            s_top[r1] = make_uint4(p21, p22, p23, p24);
        }
        __syncthreads();

        // ---- Phase A: uniform direct emission; queue hard rows ----
        {
            const int rloc = tid >> 1;
            const int half = tid & 1;
            const int row  = tile * TILE_M + rloc;
            uint4 K = s_top[rloc];
            float d1 = __uint_as_float(K.x & MASKH);
            float d2 = __uint_as_float(K.y & MASKH);
            float d4 = __uint_as_float(K.w & MASKH);
            int bidx = (int)(K.x & 511u);
            if (d2 - d1 >= MARGIN) {
                if (half == 0) {
                    out_idx[row] = (float)bidx;
                    atomicAdd(&s_hist[bidx], 1);
                    // truncation-bias compensation: +half granule (2^9 ulps)
                    loss_acc += d1 - KEYBIAS + s_xn[rloc]
                              + __uint_as_float(K.x & 0xFF800000u) * 3.0517578125e-05f;
                }
                float* oq = out_q + (size_t)row * DDIM;
                uint32_t ebase = (uint32_t)bidx * 128u;
                uint32_t xe = ((uint32_t)bidx & 7u) * 16u;
#pragma unroll
                for (int d = half * 32; d < half * 32 + 32; d += 4) {
                    uint32_t oA = ebase + (pb((uint32_t)d) ^ xe);
                    uint32_t oB = ebase + (pb((uint32_t)d + 2) ^ xe);
                    __half2 h01 = *(__half2*)(sm + SO_EH + oA);
                    __half2 h23 = *(__half2*)(sm + SO_EH + oB);
                    __half2 l01 = *(__half2*)(sm + SO_EL + oA);
                    __half2 l23 = *(__half2*)(sm + SO_EL + oB);
                    float q0 = __half2float(h01.x) + __half2float(l01.x);
                    float q1 = __half2float(h01.y) + __half2float(l01.y);
                    float q2 = __half2float(h23.x) + __half2float(l23.x);
                    float q3 = __half2float(h23.y) + __half2float(l23.y);
                    *reinterpret_cast<float4*>(oq + d) = make_float4(q0, q1, q2, q3);
                }
            } else if (half == 0) {
                if (d4 - d1 >= MARGIN) {
                    int p = atomicAdd(s_qn, 1);
                    s_que[p] = rloc;
                } else {
                    int p = atomicAdd(s_qn2, 1);
                    s_que2[p] = rloc;
                }
            }
        }
        __syncthreads();

        // ---- Phase B: duel queue, one row per WARP (uniform lanes) ----
        {
            const int qn = *s_qn;
            for (int j = wid; j < qn; j += 16) {
                const int rloc = s_que[j];
                const int row  = tile * TILE_M + rloc;
                uint4 K = s_top[rloc];
                int i1 = (int)(K.x & 511u), i2 = (int)(K.y & 511u), i3 = (int)(K.z & 511u);
                const float* xr = x + (size_t)row * DDIM;
                float2 xv = __ldg((const float2*)(xr + 2 * lane));
                uint32_t pbo = pb((uint32_t)(2 * lane));
                float p1, p2, p3;
                {
                    uint32_t o1 = (uint32_t)i1 * 128u + (pbo ^ (((uint32_t)i1 & 7u) * 16u));
                    uint32_t o2 = (uint32_t)i2 * 128u + (pbo ^ (((uint32_t)i2 & 7u) * 16u));
                    uint32_t o3 = (uint32_t)i3 * 128u + (pbo ^ (((uint32_t)i3 & 7u) * 16u));
                    __half2 h1v = *(__half2*)(sm + SO_EH + o1);
                    __half2 l1v = *(__half2*)(sm + SO_EL + o1);
                    __half2 h2v = *(__half2*)(sm + SO_EH + o2);
                    __half2 l2v = *(__half2*)(sm + SO_EL + o2);
                    __half2 h3v = *(__half2*)(sm + SO_EH + o3);
                    __half2 l3v = *(__half2*)(sm + SO_EL + o3);
                    float a0 = xv.x - (__half2float(h1v.x) + __half2float(l1v.x));
                    float a1 = xv.y - (__half2float(h1v.y) + __half2float(l1v.y));
                    p1 = fmaf(a0, a0, a1 * a1);
                    float b0 = xv.x - (__half2float(h2v.x) + __half2float(l2v.x));
                    float b1 = xv.y - (__half2float(h2v.y) + __half2float(l2v.y));
                    p2 = fmaf(b0, b0, b1 * b1);
                    float cc0 = xv.x - (__half2float(h3v.x) + __half2float(l3v.x));
                    float cc1 = xv.y - (__half2float(h3v.y) + __half2float(l3v.y));
                    p3 = fmaf(cc0, cc0, cc1 * cc1);
                }
#pragma unroll
                for (int o = 16; o > 0; o >>= 1) {
                    p1 += __shfl_xor_sync(0xffffffffu, p1, o);
                    p2 += __shfl_xor_sync(0xffffffffu, p2, o);
                    p3 += __shfl_xor_sync(0xffffffffu, p3, o);
                }
                int bidx = i1; float be = p1;
                if (p2 < be || (p2 == be && i2 < bidx)) { be = p2; bidx = i2; }
                if (p3 < be || (p3 == be && i3 < bidx)) { be = p3; bidx = i3; }
                // emit q: each lane writes its 2 dims
                uint32_t oe = (uint32_t)bidx * 128u + (pbo ^ (((uint32_t)bidx & 7u) * 16u));
                __half2 hv = *(__half2*)(sm + SO_EH + oe);
                __half2 lv = *(__half2*)(sm + SO_EL + oe);
                float q0 = __half2float(hv.x) + __half2float(lv.x);
                float q1 = __half2float(hv.y) + __half2float(lv.y);
                *(float2*)(out_q + (size_t)row * DDIM + 2 * lane) = make_float2(q0, q1);
                if (lane == 0) {
                    out_idx[row] = (float)bidx;
                    atomicAdd(&s_hist[bidx], 1);
                    loss_acc += be;
                }
            }
        }
        __syncthreads();

        // ---- Phase C: rare full exact rescan, one row per block ----
        {
            const int qn2 = *s_qn2;
            for (int qi = 0; qi < qn2; qi++) {
                if (tid == 0) *s_b64 = 0xFFFFFFFFFFFFFFFFull;
                __syncthreads();
                const int rloc = s_que2[qi];
                const int row  = tile * TILE_M + rloc;
                const float* xr = x + (size_t)row * DDIM;
                // thread tid handles code tid
                float a0 = 0.f, a1 = 0.f;
                uint32_t ebase = (uint32_t)tid * 128u;
                uint32_t xe = ((uint32_t)tid & 7u) * 16u;
#pragma unroll 8
                for (int p = 0; p < 32; p++) {
                    uint32_t off = ebase + (((((uint32_t)p & 3u) * 32u) + (((uint32_t)p >> 3) * 8u)
                                            + ((((uint32_t)p >> 2) & 1u) * 4u)) ^ xe);
                    __half2 h2v = *(const __half2*)(sm + SO_EH + off);
                    __half2 l2v = *(const __half2*)(sm + SO_EL + off);
                    float2 xv = __ldg((const float2*)(xr + 2 * p));
                    float t0 = xv.x - (__half2float(h2v.x) + __half2float(l2v.x));
                    float t1 = xv.y - (__half2float(h2v.y) + __half2float(l2v.y));
                    a0 = fmaf(t0, t0, a0);
                    a1 = fmaf(t1, t1, a1);
                }
                float dv = a0 + a1;
                unsigned long long loc =
                    (((unsigned long long)__float_as_uint(dv)) << 32) | (unsigned)tid;
#pragma unroll
                for (int o = 16; o > 0; o >>= 1) {
                    unsigned long long ov = __shfl_xor_sync(0xffffffffu, loc, o);
                    loc = min(loc, ov);
                }
                if (lane == 0) atomicMin(s_b64, loc);
                __syncthreads();
                const unsigned long long win = *s_b64;
                const int bidx = (int)(win & 511u);
                if (tid < 32) {
                    int d = tid * 2;
                    uint32_t eb2 = (uint32_t)bidx * 128u;
                    uint32_t xe2 = ((uint32_t)bidx & 7u) * 16u;
                    uint32_t off = eb2 + (pb((uint32_t)d) ^ xe2);
                    __half2 h2v = *(__half2*)(sm + SO_EH + off);
                    __half2 l2v = *(__half2*)(sm + SO_EL + off);
                    float q0 = __half2float(h2v.x) + __half2float(l2v.x);
                    float q1 = __half2float(h2v.y) + __half2float(l2v.y);
                    *(float2*)(out_q + (size_t)row * DDIM + d) = make_float2(q0, q1);
                }
                if (tid == 0) {
                    out_idx[row] = (float)bidx;
                    atomicAdd(&s_hist[bidx], 1);
                    loss_acc += __uint_as_float((uint32_t)(win >> 32));
                }
                __syncthreads();
            }
        }
        __syncthreads();
    }

#pragma unroll
    for (int o = 16; o > 0; o >>= 1)
        loss_acc += __shfl_xor_sync(0xffffffffu, loss_acc, o);
    if (lane == 0) atomicAdd(&g_loss, loss_acc);

    {
        int c = s_hist[tid];
        if (c) atomicAdd(&g_cluster[tid], (float)c);
    }
}

// ---------------------------------------------------------------------------
__global__ __launch_bounds__(512)
void k_dw(const float* __restrict__ x, const float* __restrict__ idxf) {
    extern __shared__ float sdw[];          // [64][513]
    const int t = threadIdx.x;
    const int d = t & 63;
    const int rs = t >> 6;
    const int base = blockIdx.x * 1024;
    for (int i = t; i < 64 * 513; i += 512) sdw[i] = 0.f;
    __syncthreads();
#pragma unroll 1
    for (int j0 = 0; j0 < 1024; j0 += 32) {
        float xv[4]; int cd[4];
#pragma unroll
        for (int u = 0; u < 4; u++) {
            int r = base + j0 + rs * 4 + u;
            cd[u] = (int)__ldg(&idxf[r]);
            xv[u] = __ldg(&x[(size_t)r * 64 + d]);
        }
        float s = xv[0]; int c = cd[0];
#pragma unroll
        for (int u = 1; u < 4; u++) {
            if (cd[u] == c) s += xv[u];
            else { atomicAdd(&sdw[d * 513 + c], s); c = cd[u]; s = xv[u]; }
        }
        atomicAdd(&sdw[d * 513 + c], s);
    }
    __syncthreads();
    for (int i = t; i < 64 * 512; i += 512) {
        int dd = i >> 9, k = i & 511;
        float v = sdw[dd * 513 + k];
        if (v != 0.f) atomicAdd(&g_dw[i], v);
    }
}

// ---------------------------------------------------------------------------
__global__ void k_final(const float* __restrict__ ehc,
                        const float* __restrict__ ehd,
                        const int* __restrict__ counter,
                        float* __restrict__ out) {
    __shared__ float red_n[512];
    __shared__ float red_p[512];

    const int k = threadIdx.x;
    const int d = blockIdx.x;
    const float one_minus_decay = 0.01f;

    float cn = g_cluster[k];
    float t = (float)(*counter + 1);
    float debias = 1.0f - powf(0.99f, t);
    float inv_debias = 1.0f / debias;

    float h    = ehc[k];
    float nhc  = h - (h - cn) * one_minus_decay;
    float avgc = nhc * inv_debias;

    red_n[k] = avgc;
    float p = cn * (1.0f / (float)NROWS);
    red_p[k] = (d == 0) ? p * logf(p + 1e-10f) : 0.f;
    __syncthreads();
#pragma unroll
    for (int s = 256; s > 0; s >>= 1) {
        if (k < s) { red_n[k] += red_n[k + s]; red_p[k] += red_p[k + s]; }
        __syncthreads();
    }
    float n_total = red_n[0];
    float smoothed = (avgc + 1e-5f) / (n_total + (float)KCB * 1e-5f) * n_total;

    float dw  = g_dw[d * KCB + k];
    float hd  = ehd[d * KCB + k];
    float nhd = hd - (hd - dw) * one_minus_decay;
    out[OFF_EMB + d * KCB + k] = (nhd * inv_debias) / smoothed;

    if (d == 0 && k == 0) {
        out[OFF_LOSS] = 0.25f * g_loss / (float)((size_t)NROWS * DDIM);
        out[OFF_PERP] = expf(-red_p[0]);
    }
}

// ---------------------------------------------------------------------------
extern "C" void kernel_launch(void* const* d_in, const int* in_sizes, int n_in,
                              void* d_out, int out_size) {
    const float* x       = (const float*)d_in[0];
    const float* emb     = (const float*)d_in[1];
    const float* ehc     = (const float*)d_in[2];
    const float* ehd     = (const float*)d_in[3];
    const int*   counter = (const int*)d_in[4];
    float* out = (float*)d_out;

    cudaFuncSetAttribute(k_main, cudaFuncAttributeMaxDynamicSharedMemorySize,
                         (int)SMEM_SZ);
    cudaFuncSetAttribute(k_dw, cudaFuncAttributeMaxDynamicSharedMemorySize,
                         64 * 513 * 4);

    k_prep<<<8, 512>>>(emb);
    k_zero_a<<<32, 512>>>();
    k_zero_b<<<32, 512>>>();
    k_main<<<GRID_MAIN, THREADS, SMEM_SZ>>>(x, emb, out + OFF_Q, out + OFF_IDX);
    k_dw<<<128, 512, 64 * 513 * 4>>>(x, out + OFF_IDX);
    k_final<<<64, 512>>>(ehc, ehd, counter, out);
}

// round 10
// speedup vs baseline: 2.9839x; 1.0005x over previous
#include <cuda_runtime.h>
#include <cuda_fp16.h>
#include <cstdint>
#include <math.h>

#define NROWS 131072
#define DDIM  64
#define KCB   512
#define TILE_M 256
#define NTILES (NROWS / TILE_M)     // 512
#define GRID_MAIN 148
#define THREADS 512

#define OFF_Q    0
#define OFF_LOSS (NROWS * DDIM)
#define OFF_PERP (OFF_LOSS + 1)
#define OFF_EMB  (OFF_PERP + 1)
#define OFF_IDX  (OFF_EMB + DDIM * KCB)

#define MARGIN 0.15625f
#define MASKH  0xFFFFFE00u
#define KEYBIAS 256.0f
#define SENT 0x7F7FFFFFu

__device__ float g_dw[DDIM * KCB];
__device__ float g_cluster[KCB];
__device__ float g_loss;
__device__ float g_enorm[KCB];

__device__ __forceinline__ uint32_t pb(uint32_t d) {
    return ((d >> 1) & 3u) * 32u + (d >> 4) * 8u + ((d >> 3) & 1u) * 4u + (d & 1u) * 2u;
}

// smem layout (bytes)
#define SO_EH    0u          // 65536
#define SO_EL    65536u      // 65536
#define SO_XH    131072u     // 32768
#define SO_EN2   163840u     // 2048
#define SO_XN    165888u     // 1024
#define SO_TOP   166912u     // 4096
#define SO_HIST  171008u     // 2048
#define SO_QUE   173056u     // 1024 duel queue
#define SO_QUE2  174080u     // 1024 rescan queue
#define SO_QN    175104u     // 4
#define SO_QN2   175108u     // 4
#define SO_B64   175112u     // 8
#define SMEM_SZ  175136u

__device__ __forceinline__ void mma_f16(float* d, uint32_t a0, uint32_t a1,
                                        uint32_t a2, uint32_t a3,
                                        uint32_t b0, uint32_t b1) {
    asm volatile(
        "mma.sync.aligned.m16n8k16.row.col.f32.f16.f16.f32 "
        "{%0,%1,%2,%3}, {%4,%5,%6,%7}, {%8,%9}, {%0,%1,%2,%3};\n"
        : "+f"(d[0]), "+f"(d[1]), "+f"(d[2]), "+f"(d[3])
        : "r"(a0), "r"(a1), "r"(a2), "r"(a3), "r"(b0), "r"(b1));
}

// exact sorted top-3 insert: 5 IMNMX
__device__ __forceinline__ void ins3(uint32_t& m1, uint32_t& m2, uint32_t& m3,
                                     uint32_t k) {
    uint32_t h1 = max(m1, k); m1 = min(m1, k);
    uint32_t h2 = max(m2, h1); m2 = min(m2, h1);
    m3 = min(m3, h2);
}
__device__ __forceinline__ uint32_t mkkey(float dist, uint32_t n) {
    uint32_t r;
    asm("bfi.b32 %0, %1, %2, 0, 9;" : "=r"(r) : "r"(n), "r"(__float_as_uint(dist)));
    return r;
}

// One 64-code block: MMA + key inserts into the given per-row top-3 chains.
__device__ __forceinline__ void do_kb(
    const char* sm, int kb, int g, int q,
    const uint4& A0a, const uint4& A0b, const uint4& A1a, const uint4& A1b,
    const float* s_en2, uint32_t c0, uint32_t c1,
    uint32_t& m11, uint32_t& m12, uint32_t& m13,
    uint32_t& m21, uint32_t& m22, uint32_t& m23)
{
    float acc[8][4];
#pragma unroll
    for (int nt = 0; nt < 8; nt++)
#pragma unroll
        for (int j = 0; j < 4; j++) acc[nt][j] = 0.f;

#pragma unroll
    for (int nt = 0; nt < 8; nt++) {
        uint32_t rowb = (uint32_t)(kb * 64 + nt * 8 + g) * 128u;
        uint4 B0 = *(const uint4*)(sm + SO_EH + rowb + c0);
        uint4 B1 = *(const uint4*)(sm + SO_EH + rowb + c1);
        mma_f16(acc[nt], A0a.x, A1a.x, A0a.y, A1a.y, B0.x, B0.y);
        mma_f16(acc[nt], A0a.z, A1a.z, A0a.w, A1a.w, B0.z, B0.w);
        mma_f16(acc[nt], A0b.x, A1b.x, A0b.y, A1b.y, B1.x, B1.y);
        mma_f16(acc[nt], A0b.z, A1b.z, A0b.w, A1b.w, B1.z, B1.w);
    }
#pragma unroll
    for (int nt = 0; nt < 8; nt++) {
        uint32_t n0 = (uint32_t)(kb * 64 + nt * 8 + q * 2);
        float2 en = *(const float2*)&s_en2[n0];
        uint32_t k0 = mkkey(fmaf(-2.f, acc[nt][0], en.x), n0);
        uint32_t k1 = mkkey(fmaf(-2.f, acc[nt][1], en.y), n0 + 1);
        uint32_t k2 = mkkey(fmaf(-2.f, acc[nt][2], en.x), n0);
        uint32_t k3 = mkkey(fmaf(-2.f, acc[nt][3], en.y), n0 + 1);
        ins3(m11, m12, m13, k0);
        ins3(m11, m12, m13, k1);
        ins3(m21, m22, m23, k2);
        ins3(m21, m22, m23, k3);
    }
}

// ---------------------------------------------------------------------------
__global__ void k_prep(const float* __restrict__ emb) {
    __shared__ float red[8][64];
    const int t = threadIdx.x, b = blockIdx.x;
    const int kk = t & 63, part = t >> 6;
    const int k = b * 64 + kk;
    float s = 0.f;
#pragma unroll
    for (int j = 0; j < 8; j++) {
        float e = emb[(part * 8 + j) * KCB + k];
        s = fmaf(e, e, s);
    }
    red[part][kk] = s;
    __syncthreads();
    if (t < 64) {
        float tot = red[0][t];
#pragma unroll
        for (int p = 1; p < 8; p++) tot += red[p][t];
        g_enorm[b * 64 + t] = tot;
    }
    if (b == 0) {
        g_cluster[t] = 0.f;
        if (t == 0) g_loss = 0.f;
    }
}
__global__ void k_zero_a() { g_dw[blockIdx.x * 512 + threadIdx.x] = 0.f; }
__global__ void k_zero_b() { g_dw[16384 + blockIdx.x * 512 + threadIdx.x] = 0.f; }

// ---------------------------------------------------------------------------
__global__ __launch_bounds__(THREADS, 1)
void k_main(const float* __restrict__ x, const float* __restrict__ emb,
            float* __restrict__ out_q, float* __restrict__ out_idx) {
    extern __shared__ __align__(1024) char sm[];
    const int tid  = threadIdx.x;
    const int wid  = tid >> 5;
    const int lane = tid & 31;
    const int g    = lane >> 2;
    const int q    = lane & 3;

    float* s_en2  = (float*)(sm + SO_EN2);
    float* s_xn   = (float*)(sm + SO_XN);
    uint4* s_top  = (uint4*)(sm + SO_TOP);
    int*   s_hist = (int*)(sm + SO_HIST);
    int*   s_que  = (int*)(sm + SO_QUE);
    int*   s_que2 = (int*)(sm + SO_QUE2);
    int*   s_qn   = (int*)(sm + SO_QN);
    int*   s_qn2  = (int*)(sm + SO_QN2);
    unsigned long long* s_b64 = (unsigned long long*)(sm + SO_B64);

    for (int i = tid; i < DDIM * KCB; i += THREADS) {
        uint32_t d = (uint32_t)i >> 9, k = (uint32_t)i & 511u;
        float e = emb[i];
        __half h = __float2half_rn(e);
        __half l = __float2half_rn(e - __half2float(h));
        uint32_t off = k * 128u + (pb(d) ^ ((k & 7u) * 16u));
        *(__half*)(sm + SO_EH + off) = h;
        *(__half*)(sm + SO_EL + off) = l;
    }
    s_en2[tid] = g_enorm[tid] + KEYBIAS;
    s_hist[tid] = 0;
    __syncthreads();

    const int r0 = wid * 16 + g;
    const int r1 = r0 + 8;
    const uint32_t c0 = ((uint32_t)q * 32u) ^ ((uint32_t)g * 16u);
    const uint32_t c1 = ((uint32_t)q * 32u + 16u) ^ ((uint32_t)g * 16u);

    float loss_acc = 0.f;

    for (int tile = blockIdx.x; tile < NTILES; tile += gridDim.x) {
        const float* xt = x + (size_t)tile * TILE_M * DDIM;

        if (tid == 0) { *s_qn = 0; *s_qn2 = 0; }
#pragma unroll
        for (int it = 0; it < 8; it++) {
            int i = it * THREADS + tid;
            float4 v = ((const float4*)xt)[i];
            uint32_t r = (uint32_t)i >> 4, c = ((uint32_t)i & 15u) * 4u;
            uint32_t xw = (r & 7u) * 16u;
            *(__half2*)(sm + SO_XH + r * 128u + (pb(c) ^ xw)) =
                __floats2half2_rn(v.x, v.y);
            *(__half2*)(sm + SO_XH + r * 128u + (pb(c + 2) ^ xw)) =
                __floats2half2_rn(v.z, v.w);
            float pn = fmaf(v.x, v.x, fmaf(v.y, v.y, fmaf(v.z, v.z, v.w * v.w)));
            pn += __shfl_xor_sync(0xffffffffu, pn, 1);
            pn += __shfl_xor_sync(0xffffffffu, pn, 2);
            pn += __shfl_xor_sync(0xffffffffu, pn, 4);
            pn += __shfl_xor_sync(0xffffffffu, pn, 8);
            if ((tid & 15) == 0) s_xn[r] = pn;
        }
        __syncthreads();

        uint4 A0a = *(const uint4*)(sm + SO_XH + (uint32_t)r0 * 128u + c0);
        uint4 A0b = *(const uint4*)(sm + SO_XH + (uint32_t)r0 * 128u + c1);
        uint4 A1a = *(const uint4*)(sm + SO_XH + (uint32_t)r1 * 128u + c0);
        uint4 A1b = *(const uint4*)(sm + SO_XH + (uint32_t)r1 * 128u + c1);

        // per-row dual top-3 chains over disjoint halves (even kb / odd kb)
        uint32_t e11 = SENT, e12 = SENT, e13 = SENT;   // row0, even kb
        uint32_t o11 = SENT, o12 = SENT, o13 = SENT;   // row0, odd kb
        uint32_t e21 = SENT, e22 = SENT, e23 = SENT;   // row1, even kb
        uint32_t o21 = SENT, o22 = SENT, o23 = SENT;   // row1, odd kb

#pragma unroll 1
        for (int kbp = 0; kbp < 4; kbp++) {
            do_kb(sm, 2 * kbp,     g, q, A0a, A0b, A1a, A1b, s_en2, c0, c1,
                  e11, e12, e13, e21, e22, e23);
            do_kb(sm, 2 * kbp + 1, g, q, A0a, A0b, A1a, A1b, s_en2, c0, c1,
                  o11, o12, o13, o21, o22, o23);
        }

        // merge odd chain into even chain (disjoint subsets -> exact top-3)
        ins3(e11, e12, e13, o11); ins3(e11, e12, e13, o12); ins3(e11, e12, e13, o13);
        ins3(e21, e22, e23, o21); ins3(e21, e22, e23, o22); ins3(e21, e22, e23, o23);

        // merge across quad lanes
#pragma unroll
        for (int o = 1; o <= 2; o <<= 1) {
            uint32_t q1 = __shfl_xor_sync(0xffffffffu, e11, o);
            uint32_t q2 = __shfl_xor_sync(0xffffffffu, e12, o);
            uint32_t q3 = __shfl_xor_sync(0xffffffffu, e13, o);
            ins3(e11, e12, e13, q1);
            ins3(e11, e12, e13, q2);
            ins3(e11, e12, e13, q3);
            q1 = __shfl_xor_sync(0xffffffffu, e21, o);
            q2 = __shfl_xor_sync(0xffffffffu, e22, o);
            q3 = __shfl_xor_sync(0xffffffffu, e23, o);
            ins3(e21, e22, e23, q1);
            ins3(e21, e22, e23, q2);
            ins3(e21, e22, e23, q3);
        }
        if (q == 0) {
            s_top[r0] = make_uint4(e11, e12, e13, 0u);
            s_top[r1] = make_uint4(e21, e22, e23, 0u);
        }
        __syncthreads();

        // ---- Phase A: uniform direct emission; queue hard rows ----
        {
            const int rloc = tid >> 1;
            const int half = tid & 1;
            const int row  = tile * TILE_M + rloc;
            uint4 K = s_top[rloc];
            float d1 = __uint_as_float(K.x & MASKH);
            float d2 = __uint_as_float(K.y & MASKH);
            float d3 = __uint_as_float(K.z & MASKH);
            int bidx = (int)(K.x & 511u);
            if (d2 - d1 >= MARGIN) {
                if (half == 0) {
                    out_idx[row] = (float)bidx;
                    atomicAdd(&s_hist[bidx], 1);
                    loss_acc += d1 - KEYBIAS + s_xn[rloc]
                              + __uint_as_float(K.x & 0xFF800000u) * 3.0517578125e-05f;
                }
                float* oq = out_q + (size_t)row * DDIM;
                uint32_t ebase = (uint32_t)bidx * 128u;
                uint32_t xe = ((uint32_t)bidx & 7u) * 16u;
#pragma unroll
                for (int d = half * 32; d < half * 32 + 32; d += 4) {
                    uint32_t oA = ebase + (pb((uint32_t)d) ^ xe);
                    uint32_t oB = ebase + (pb((uint32_t)d + 2) ^ xe);
                    __half2 h01 = *(__half2*)(sm + SO_EH + oA);
                    __half2 h23 = *(__half2*)(sm + SO_EH + oB);
                    __half2 l01 = *(__half2*)(sm + SO_EL + oA);
                    __half2 l23 = *(__half2*)(sm + SO_EL + oB);
                    float q0 = __half2float(h01.x) + __half2float(l01.x);
                    float q1 = __half2float(h01.y) + __half2float(l01.y);
                    float q2 = __half2float(h23.x) + __half2float(l23.x);
                    float q3 = __half2float(h23.y) + __half2float(l23.y);
                    *reinterpret_cast<float4*>(oq + d) = make_float4(q0, q1, q2, q3);
                }
            } else if (half == 0) {
                if (d3 - d1 >= MARGIN) {
                    int p = atomicAdd(s_qn, 1);
                    s_que[p] = rloc;
                } else {
                    int p = atomicAdd(s_qn2, 1);
                    s_que2[p] = rloc;
                }
            }
        }
        __syncthreads();

        // ---- Phase B: 2-candidate exact duel, one row per WARP ----
        {
            const int qn = *s_qn;
            for (int j = wid; j < qn; j += 16) {
                const int rloc = s_que[j];
                const int row  = tile * TILE_M + rloc;
                uint4 K = s_top[rloc];
                int i1 = (int)(K.x & 511u), i2 = (int)(K.y & 511u);
                const float* xr = x + (size_t)row * DDIM;
                float2 xv = __ldg((const float2*)(xr + 2 * lane));
                uint32_t pbo = pb((uint32_t)(2 * lane));
                float p1, p2;
                {
                    uint32_t o1 = (uint32_t)i1 * 128u + (pbo ^ (((uint32_t)i1 & 7u) * 16u));
                    uint32_t o2 = (uint32_t)i2 * 128u + (pbo ^ (((uint32_t)i2 & 7u) * 16u));
                    __half2 h1v = *(__half2*)(sm + SO_EH + o1);
                    __half2 l1v = *(__half2*)(sm + SO_EL + o1);
                    __half2 h2v = *(__half2*)(sm + SO_EH + o2);
                    __half2 l2v = *(__half2*)(sm + SO_EL + o2);
                    float a0 = xv.x - (__half2float(h1v.x) + __half2float(l1v.x));
                    float a1 = xv.y - (__half2float(h1v.y) + __half2float(l1v.y));
                    p1 = fmaf(a0, a0, a1 * a1);
                    float b0 = xv.x - (__half2float(h2v.x) + __half2float(l2v.x));
                    float b1 = xv.y - (__half2float(h2v.y) + __half2float(l2v.y));
                    p2 = fmaf(b0, b0, b1 * b1);
                }
#pragma unroll
                for (int o = 16; o > 0; o >>= 1) {
                    p1 += __shfl_xor_sync(0xffffffffu, p1, o);
                    p2 += __shfl_xor_sync(0xffffffffu, p2, o);
                }
                int bidx = i1; float be = p1;
                if (p2 < be || (p2 == be && i2 < bidx)) { be = p2; bidx = i2; }
                uint32_t oe = (uint32_t)bidx * 128u + (pbo ^ (((uint32_t)bidx & 7u) * 16u));
                __half2 hv = *(__half2*)(sm + SO_EH + oe);
                __half2 lv = *(__half2*)(sm + SO_EL + oe);
                float q0 = __half2float(hv.x) + __half2float(lv.x);
                float q1 = __half2float(hv.y) + __half2float(lv.y);
                *(float2*)(out_q + (size_t)row * DDIM + 2 * lane) = make_float2(q0, q1);
                if (lane == 0) {
                    out_idx[row] = (float)bidx;
                    atomicAdd(&s_hist[bidx], 1);
                    loss_acc += be;
                }
            }
        }
        __syncthreads();

        // ---- Phase C: rare full exact rescan, one row per block ----
        {
            const int qn2 = *s_qn2;
            for (int qi = 0; qi < qn2; qi++) {
                if (tid == 0) *s_b64 = 0xFFFFFFFFFFFFFFFFull;
                __syncthreads();
                const int rloc = s_que2[qi];
                const int row  = tile * TILE_M + rloc;
                const float* xr = x + (size_t)row * DDIM;
                float a0 = 0.f, a1 = 0.f;
                uint32_t ebase = (uint32_t)tid * 128u;
                uint32_t xe = ((uint32_t)tid & 7u) * 16u;
#pragma unroll 8
                for (int p = 0; p < 32; p++) {
                    uint32_t off = ebase + (((((uint32_t)p & 3u) * 32u) + (((uint32_t)p >> 3) * 8u)
                                            + ((((uint32_t)p >> 2) & 1u) * 4u)) ^ xe);
                    __half2 h2v = *(const __half2*)(sm + SO_EH + off);
                    __half2 l2v = *(const __half2*)(sm + SO_EL + off);
                    float2 xv = __ldg((const float2*)(xr + 2 * p));
                    float t0 = xv.x - (__half2float(h2v.x) + __half2float(l2v.x));
                    float t1 = xv.y - (__half2float(h2v.y) + __half2float(l2v.y));
                    a0 = fmaf(t0, t0, a0);
                    a1 = fmaf(t1, t1, a1);
                }
                float dv = a0 + a1;
                unsigned long long loc =
                    (((unsigned long long)__float_as_uint(dv)) << 32) | (unsigned)tid;
#pragma unroll
                for (int o = 16; o > 0; o >>= 1) {
                    unsigned long long ov = __shfl_xor_sync(0xffffffffu, loc, o);
                    loc = min(loc, ov);
                }
                if (lane == 0) atomicMin(s_b64, loc);
                __syncthreads();
                const unsigned long long win = *s_b64;
                const int bidx = (int)(win & 511u);
                if (tid < 32) {
                    int d = tid * 2;
                    uint32_t eb2 = (uint32_t)bidx * 128u;
                    uint32_t xe2 = ((uint32_t)bidx & 7u) * 16u;
                    uint32_t off = eb2 + (pb((uint32_t)d) ^ xe2);
                    __half2 h2v = *(__half2*)(sm + SO_EH + off);
                    __half2 l2v = *(__half2*)(sm + SO_EL + off);
                    float q0 = __half2float(h2v.x) + __half2float(l2v.x);
                    float q1 = __half2float(h2v.y) + __half2float(l2v.y);
                    *(float2*)(out_q + (size_t)row * DDIM + d) = make_float2(q0, q1);
                }
                if (tid == 0) {
                    out_idx[row] = (float)bidx;
                    atomicAdd(&s_hist[bidx], 1);
                    loss_acc += __uint_as_float((uint32_t)(win >> 32));
                }
                __syncthreads();
            }
        }
        __syncthreads();
    }

#pragma unroll
    for (int o = 16; o > 0; o >>= 1)
        loss_acc += __shfl_xor_sync(0xffffffffu, loss_acc, o);
    if (lane == 0) atomicAdd(&g_loss, loss_acc);

    {
        int c = s_hist[tid];
        if (c) atomicAdd(&g_cluster[tid], (float)c);
    }
}

// ---------------------------------------------------------------------------
__global__ __launch_bounds__(512)
void k_dw(const float* __restrict__ x, const float* __restrict__ idxf) {
    extern __shared__ float sdw[];          // [64][513]
    const int t = threadIdx.x;
    const int d = t & 63;
    const int rs = t >> 6;
    const int base = blockIdx.x * 1024;
    for (int i = t; i < 64 * 513; i += 512) sdw[i] = 0.f;
    __syncthreads();
#pragma unroll 1
    for (int j0 = 0; j0 < 1024; j0 += 32) {
        float xv[4]; int cd[4];
#pragma unroll
        for (int u = 0; u < 4; u++) {
            int r = base + j0 + rs * 4 + u;
            cd[u] = (int)__ldg(&idxf[r]);
            xv[u] = __ldg(&x[(size_t)r * 64 + d]);
        }
        float s = xv[0]; int c = cd[0];
#pragma unroll
        for (int u = 1; u < 4; u++) {
            if (cd[u] == c) s += xv[u];
            else { atomicAdd(&sdw[d * 513 + c], s); c = cd[u]; s = xv[u]; }
        }
        atomicAdd(&sdw[d * 513 + c], s);
    }
    __syncthreads();
    for (int i = t; i < 64 * 512; i += 512) {
        int dd = i >> 9, k = i & 511;
        float v = sdw[dd * 513 + k];
        if (v != 0.f) atomicAdd(&g_dw[i], v);
    }
}

// ---------------------------------------------------------------------------
__global__ void k_final(const float* __restrict__ ehc,
                        const float* __restrict__ ehd,
                        const int* __restrict__ counter,
                        float* __restrict__ out) {
    __shared__ float red_n[512];
    __shared__ float red_p[512];

    const int k = threadIdx.x;
    const int d = blockIdx.x;
    const float one_minus_decay = 0.01f;

    float cn = g_cluster[k];
    float t = (float)(*counter + 1);
    float debias = 1.0f - powf(0.99f, t);
    float inv_debias = 1.0f / debias;

    float h    = ehc[k];
    float nhc  = h - (h - cn) * one_minus_decay;
    float avgc = nhc * inv_debias;

    red_n[k] = avgc;
    float p = cn * (1.0f / (float)NROWS);
    red_p[k] = (d == 0) ? p * logf(p + 1e-10f) : 0.f;
    __syncthreads();
#pragma unroll
    for (int s = 256; s > 0; s >>= 1) {
        if (k < s) { red_n[k] += red_n[k + s]; red_p[k] += red_p[k + s]; }
        __syncthreads();
    }
    float n_total = red_n[0];
    float smoothed = (avgc + 1e-5f) / (n_total + (float)KCB * 1e-5f) * n_total;

    float dw  = g_dw[d * KCB + k];
    float hd  = ehd[d * KCB + k];
    float nhd = hd - (hd - dw) * one_minus_decay;
    out[OFF_EMB + d * KCB + k] = (nhd * inv_debias) / smoothed;

    if (d == 0 && k == 0) {
        out[OFF_LOSS] = 0.25f * g_loss / (float)((size_t)NROWS * DDIM);
        out[OFF_PERP] = expf(-red_p[0]);
    }
}

// ---------------------------------------------------------------------------
extern "C" void kernel_launch(void* const* d_in, const int* in_sizes, int n_in,
                              void* d_out, int out_size) {
    const float* x       = (const float*)d_in[0];
    const float* emb     = (const float*)d_in[1];
    const float* ehc     = (const float*)d_in[2];
    const float* ehd     = (const float*)d_in[3];
    const int*   counter = (const int*)d_in[4];
    float* out = (float*)d_out;

    cudaFuncSetAttribute(k_main, cudaFuncAttributeMaxDynamicSharedMemorySize,
                         (int)SMEM_SZ);
    cudaFuncSetAttribute(k_dw, cudaFuncAttributeMaxDynamicSharedMemorySize,
                         64 * 513 * 4);

    k_prep<<<8, 512>>>(emb);
    k_zero_a<<<32, 512>>>();
    k_zero_b<<<32, 512>>>();
    k_main<<<GRID_MAIN, THREADS, SMEM_SZ>>>(x, emb, out + OFF_Q, out + OFF_IDX);
    k_dw<<<128, 512, 64 * 513 * 4>>>(x, out + OFF_IDX);
    k_final<<<64, 512>>>(ehc, ehd, counter, out);
}